// round 2
// baseline (speedup 1.0000x reference)
#include <cuda_runtime.h>

#define BS_   1024
#define NE_   128
#define INDIM 512
#define EMB   512
#define NAG   32
#define NHD   8
#define HDD   64

// Scratch (static device globals — allocation-guard safe)
__device__ float g_kv[(size_t)BS_ * NE_ * 1024];   // [b*128+e][0:512)=K, [512:1024)=V (head-major)
__device__ float g_q [(size_t)BS_ * NAG * EMB];    // [b*32+a][h*64+d]
__device__ float g_at[(size_t)BS_ * NAG * EMB];    // attention output

// ---------------------------------------------------------------------------
// SGEMM (NT): C[M,N] = A[M,K] * B[N,K]^T   (A,B row-major, K contiguous)
// 128x128 tile, BK=16, 256 threads, 8x8 microtile.
// REMAP: logical row gm -> entity row (gm/32)*128 + gm%32  (agent rows of q GEMM)
// FINAL: add bias[col], zero row if rowmask[row] != 0   (rowmask is int32)
// ---------------------------------------------------------------------------
template<bool REMAP, bool FINAL>
__global__ __launch_bounds__(256)
void sgemm_nt(const float* __restrict__ A, const float* __restrict__ B,
              float* __restrict__ C, int K, int lda, int ldb, int ldc,
              const float* __restrict__ bias,
              const int* __restrict__ rowmask)
{
    __shared__ float As[16][128];
    __shared__ float Bs[16][128];

    const int tid = threadIdx.x;
    const int lr  = tid >> 2;          // 0..63
    const int lc  = (tid & 3) << 2;    // 0,4,8,12

    int gr0 = blockIdx.y * 128 + lr;
    int gr1 = gr0 + 64;
    int ar0 = REMAP ? (((gr0 >> 5) << 7) | (gr0 & 31)) : gr0;
    int ar1 = REMAP ? (((gr1 >> 5) << 7) | (gr1 & 31)) : gr1;
    const float* Ap0 = A + (size_t)ar0 * lda + lc;
    const float* Ap1 = A + (size_t)ar1 * lda + lc;
    const float* Bp0 = B + (size_t)(blockIdx.x * 128 + lr) * ldb + lc;
    const float* Bp1 = Bp0 + (size_t)64 * ldb;

    const int tx = (tid & 15) << 2;    // 0..60
    const int ty = (tid >> 4) << 2;    // 0..60

    float acc[8][8];
    #pragma unroll
    for (int i = 0; i < 8; i++)
        #pragma unroll
        for (int j = 0; j < 8; j++) acc[i][j] = 0.f;

    for (int k0 = 0; k0 < K; k0 += 16) {
        float4 a0 = *(const float4*)(Ap0 + k0);
        float4 a1 = *(const float4*)(Ap1 + k0);
        float4 b0 = *(const float4*)(Bp0 + k0);
        float4 b1 = *(const float4*)(Bp1 + k0);
        __syncthreads();
        As[lc+0][lr]    = a0.x; As[lc+1][lr]    = a0.y; As[lc+2][lr]    = a0.z; As[lc+3][lr]    = a0.w;
        As[lc+0][lr+64] = a1.x; As[lc+1][lr+64] = a1.y; As[lc+2][lr+64] = a1.z; As[lc+3][lr+64] = a1.w;
        Bs[lc+0][lr]    = b0.x; Bs[lc+1][lr]    = b0.y; Bs[lc+2][lr]    = b0.z; Bs[lc+3][lr]    = b0.w;
        Bs[lc+0][lr+64] = b1.x; Bs[lc+1][lr+64] = b1.y; Bs[lc+2][lr+64] = b1.z; Bs[lc+3][lr+64] = b1.w;
        __syncthreads();
        #pragma unroll
        for (int kk = 0; kk < 16; kk++) {
            float4 x0 = *(const float4*)&As[kk][ty];
            float4 x1 = *(const float4*)&As[kk][ty + 64];
            float4 y0 = *(const float4*)&Bs[kk][tx];
            float4 y1 = *(const float4*)&Bs[kk][tx + 64];
            float ar_[8] = {x0.x,x0.y,x0.z,x0.w,x1.x,x1.y,x1.z,x1.w};
            float br_[8] = {y0.x,y0.y,y0.z,y0.w,y1.x,y1.y,y1.z,y1.w};
            #pragma unroll
            for (int i = 0; i < 8; i++)
                #pragma unroll
                for (int j = 0; j < 8; j++)
                    acc[i][j] = fmaf(ar_[i], br_[j], acc[i][j]);
        }
    }

    #pragma unroll
    for (int i = 0; i < 8; i++) {
        int r = blockIdx.y * 128 + ((i < 4) ? (ty + i) : (ty + 60 + i));  // +64 for upper half
        bool zr = false;
        if (FINAL) zr = (rowmask[r] != 0);
        #pragma unroll
        for (int jj = 0; jj < 2; jj++) {
            int c = blockIdx.x * 128 + tx + jj * 64;
            float4 v;
            v.x = acc[i][jj*4+0]; v.y = acc[i][jj*4+1];
            v.z = acc[i][jj*4+2]; v.w = acc[i][jj*4+3];
            if (FINAL) {
                if (zr) { v.x = 0.f; v.y = 0.f; v.z = 0.f; v.w = 0.f; }
                else { v.x += bias[c]; v.y += bias[c+1]; v.z += bias[c+2]; v.w += bias[c+3]; }
            }
            *(float4*)(C + (size_t)r * ldc + c) = v;
        }
    }
}

// ---------------------------------------------------------------------------
// Fused attention: one block per (batch, head). 256 threads.
//   logits[32,128] = q[32,64] . k[128,64]^T / 8, mask -> -1e30
//   softmax over entities (all-masked row -> weights 0)
//   attn[32,64] = w[32,128] . v[128,64]
// smem: smA = q (d-major 64x32) then logits (32x128); smB = k (d-major 64x128)
//       then v (e-major 128x64). 48 KB total.  pre_mask is int32.
// ---------------------------------------------------------------------------
__global__ __launch_bounds__(256)
void attn_kernel(const float* __restrict__ q, const float* __restrict__ kv,
                 const int* __restrict__ pre_mask,
                 float* __restrict__ out)
{
    __shared__ float smA[4096];
    __shared__ float smB[8192];
    const int tid = threadIdx.x;
    const int b = blockIdx.x >> 3;
    const int h = blockIdx.x & 7;

    const float* qbase = q  + (size_t)b * (NAG * EMB) + h * HDD;
    const float* kbase = kv + (size_t)b * (NE_ * 1024) + h * HDD;
    const float* vbase = kbase + EMB;

    // load q transposed -> smA[d][a] (pitch 32)
    {
        int i = tid;
        #pragma unroll
        for (int it = 0; it < 2; it++, i += 256) {
            int a  = i >> 4;
            int d4 = (i & 15) << 2;
            float4 v = *(const float4*)(qbase + (size_t)a * EMB + d4);
            smA[(d4+0)*32 + a] = v.x;
            smA[(d4+1)*32 + a] = v.y;
            smA[(d4+2)*32 + a] = v.z;
            smA[(d4+3)*32 + a] = v.w;
        }
    }
    // load k transposed -> smB[d][e] (pitch 128)
    {
        int i = tid;
        #pragma unroll
        for (int it = 0; it < 8; it++, i += 256) {
            int e  = i >> 4;
            int d4 = (i & 15) << 2;
            float4 v = *(const float4*)(kbase + (size_t)e * 1024 + d4);
            smB[(d4+0)*128 + e] = v.x;
            smB[(d4+1)*128 + e] = v.y;
            smB[(d4+2)*128 + e] = v.z;
            smB[(d4+3)*128 + e] = v.w;
        }
    }
    __syncthreads();

    // logits: 4a x 4e per thread
    const int e0 = (tid & 31) << 2;
    const int a0 = (tid >> 5) << 2;
    float lg[4][4];
    #pragma unroll
    for (int i = 0; i < 4; i++)
        #pragma unroll
        for (int j = 0; j < 4; j++) lg[i][j] = 0.f;

    #pragma unroll 8
    for (int d = 0; d < 64; d++) {
        float4 qa = *(const float4*)&smA[d*32  + a0];
        float4 kb = *(const float4*)&smB[d*128 + e0];
        float qv[4] = {qa.x, qa.y, qa.z, qa.w};
        float kk[4] = {kb.x, kb.y, kb.z, kb.w};
        #pragma unroll
        for (int i = 0; i < 4; i++)
            #pragma unroll
            for (int j = 0; j < 4; j++)
                lg[i][j] = fmaf(qv[i], kk[j], lg[i][j]);
    }
    __syncthreads();   // everyone done reading q/k

    // masked logits -> smA[a][e] (pitch 128); reload smB with v (e-major)
    const int* mbase = pre_mask + (size_t)b * (NAG * NE_);
    #pragma unroll
    for (int i = 0; i < 4; i++) {
        int a = a0 + i;
        int4 m = *(const int4*)(mbase + a * NE_ + e0);
        float* lrow = &smA[a * 128 + e0];
        lrow[0] = m.x ? -1e30f : lg[i][0] * 0.125f;
        lrow[1] = m.y ? -1e30f : lg[i][1] * 0.125f;
        lrow[2] = m.z ? -1e30f : lg[i][2] * 0.125f;
        lrow[3] = m.w ? -1e30f : lg[i][3] * 0.125f;
    }
    {
        int i = tid;
        #pragma unroll
        for (int it = 0; it < 8; it++, i += 256) {
            int e  = i >> 4;
            int d4 = (i & 15) << 2;
            *(float4*)&smB[e*64 + d4] = *(const float4*)(vbase + (size_t)e * 1024 + d4);
        }
    }
    __syncthreads();

    // softmax: 8 threads per agent row
    {
        int a = tid >> 3;
        int l = tid & 7;
        float* row = &smA[a * 128];
        float mx = -1e30f;
        #pragma unroll
        for (int j = 0; j < 16; j++) mx = fmaxf(mx, row[l + 8*j]);
        mx = fmaxf(mx, __shfl_xor_sync(0xffffffffu, mx, 1));
        mx = fmaxf(mx, __shfl_xor_sync(0xffffffffu, mx, 2));
        mx = fmaxf(mx, __shfl_xor_sync(0xffffffffu, mx, 4));
        float ex[16];
        float sum = 0.f;
        #pragma unroll
        for (int j = 0; j < 16; j++) {
            float t = __expf(row[l + 8*j] - mx);
            ex[j] = t; sum += t;
        }
        sum += __shfl_xor_sync(0xffffffffu, sum, 1);
        sum += __shfl_xor_sync(0xffffffffu, sum, 2);
        sum += __shfl_xor_sync(0xffffffffu, sum, 4);
        float inv = (mx <= -1e29f) ? 0.f : (1.0f / sum);   // all-masked row -> 0 (NaN path)
        #pragma unroll
        for (int j = 0; j < 16; j++) row[l + 8*j] = ex[j] * inv;
    }
    __syncthreads();

    // attn = w @ v : 4a x 2d per thread
    const int d0 = (tid & 31) << 1;
    const int a1 = (tid >> 5) << 2;
    float oa[4][2];
    #pragma unroll
    for (int i = 0; i < 4; i++) { oa[i][0] = 0.f; oa[i][1] = 0.f; }

    #pragma unroll 8
    for (int e = 0; e < 128; e++) {
        float2 vv = *(const float2*)&smB[e*64 + d0];
        #pragma unroll
        for (int i = 0; i < 4; i++) {
            float w = smA[(a1 + i) * 128 + e];
            oa[i][0] = fmaf(w, vv.x, oa[i][0]);
            oa[i][1] = fmaf(w, vv.y, oa[i][1]);
        }
    }

    float* obase = out + (size_t)b * (NAG * EMB) + h * HDD;
    #pragma unroll
    for (int i = 0; i < 4; i++)
        *(float2*)(obase + (size_t)(a1 + i) * EMB + d0) = make_float2(oa[i][0], oa[i][1]);
}

// ---------------------------------------------------------------------------
// Launch: kv GEMM -> q GEMM (agent rows only) -> attention -> out GEMM
// inputs: entities, pre_mask(int32), post_mask(int32), W_in, W_out, b_out
// ---------------------------------------------------------------------------
extern "C" void kernel_launch(void* const* d_in, const int* in_sizes, int n_in,
                              void* d_out, int out_size)
{
    const float* entities  = (const float*)d_in[0];
    const int*   pre_mask  = (const int*)d_in[1];
    const int*   post_mask = (const int*)d_in[2];
    const float* W_in      = (const float*)d_in[3];
    const float* W_out     = (const float*)d_in[4];
    const float* b_out     = (const float*)d_in[5];
    float*       out       = (float*)d_out;

    float *kv_p, *q_p, *at_p;
    cudaGetSymbolAddress((void**)&kv_p, g_kv);
    cudaGetSymbolAddress((void**)&q_p,  g_q);
    cudaGetSymbolAddress((void**)&at_p, g_at);

    // K|V projection: [131072, 512] @ W_in[512:1536].T -> [131072, 1024]
    sgemm_nt<false, false><<<dim3(8, 1024), 256>>>(
        entities, W_in + 512 * 512, kv_p, 512, 512, 512, 1024, nullptr, nullptr);

    // Q projection, agent rows only: [32768, 512] @ W_in[0:512].T -> [32768, 512]
    sgemm_nt<true, false><<<dim3(4, 256), 256>>>(
        entities, W_in, q_p, 512, 512, 512, 512, nullptr, nullptr);

    // Attention per (batch, head)
    attn_kernel<<<BS_ * NHD, 256>>>(q_p, kv_p, pre_mask, at_p);

    // Output projection + bias + post-mask: [32768, 512] @ W_out.T
    sgemm_nt<false, true><<<dim3(4, 256), 256>>>(
        at_p, W_out, out, 512, 512, 512, 512, b_out, post_mask);
}

// round 4
// speedup vs baseline: 1.8346x; 1.8346x over previous
#include <cuda_runtime.h>
#include <cuda_bf16.h>
#include <cstdint>

#define BS_   1024
#define NE_   128
#define EMB   512
#define NAG   32
#define NHD   8
#define HDD   64
#define KDIM  512

// ---------------- scratch (device globals; allocation-guard safe) ----------
__device__ float g_kv[(size_t)BS_ * NE_ * 1024];   // [b*128+e][K(512)|V(512)]
__device__ float g_q [(size_t)BS_ * NAG * EMB];
__device__ float g_at[(size_t)BS_ * NAG * EMB];
__device__ __nv_bfloat16 g_ehi[(size_t)BS_ * NE_ * KDIM];
__device__ __nv_bfloat16 g_elo[(size_t)BS_ * NE_ * KDIM];
__device__ __nv_bfloat16 g_wihi[3 * EMB * KDIM];
__device__ __nv_bfloat16 g_wilo[3 * EMB * KDIM];
__device__ __nv_bfloat16 g_wohi[EMB * EMB];
__device__ __nv_bfloat16 g_wolo[EMB * EMB];
__device__ __nv_bfloat16 g_athi[(size_t)BS_ * NAG * EMB];
__device__ __nv_bfloat16 g_atlo[(size_t)BS_ * NAG * EMB];

// ---------------- helpers ----------------------------------------------------
#define CP16(dst, src) \
    asm volatile("cp.async.cg.shared.global [%0], [%1], 16;" :: "r"(dst), "l"(src) : "memory")
#define CP_COMMIT()  asm volatile("cp.async.commit_group;" ::: "memory")
#define CP_WAIT(n)   asm volatile("cp.async.wait_group %0;" :: "n"(n) : "memory")

__device__ __forceinline__ uint32_t smem_u32(const void* p) {
    uint32_t a;
    asm("{ .reg .u64 t; cvta.to.shared.u64 t, %1; cvt.u32.u64 %0, t; }" : "=r"(a) : "l"(p));
    return a;
}
__device__ __forceinline__ void mma_bf16(float* c, const uint32_t* a, const uint32_t* b) {
    asm volatile(
        "mma.sync.aligned.m16n8k16.row.col.f32.bf16.bf16.f32 "
        "{%0,%1,%2,%3}, {%4,%5,%6,%7}, {%8,%9}, {%0,%1,%2,%3};"
        : "+f"(c[0]), "+f"(c[1]), "+f"(c[2]), "+f"(c[3])
        : "r"(a[0]), "r"(a[1]), "r"(a[2]), "r"(a[3]), "r"(b[0]), "r"(b[1]));
}

// ---------------- fp32 -> bf16 hi/lo split ---------------------------------
__global__ __launch_bounds__(256)
void split_kernel(const float* __restrict__ x, __nv_bfloat16* __restrict__ hi,
                  __nv_bfloat16* __restrict__ lo, int n4)
{
    int i = blockIdx.x * 256 + threadIdx.x;
    if (i >= n4) return;
    float4 v = ((const float4*)x)[i];
    __nv_bfloat16 h0 = __float2bfloat16(v.x), h1 = __float2bfloat16(v.y);
    __nv_bfloat16 h2 = __float2bfloat16(v.z), h3 = __float2bfloat16(v.w);
    __nv_bfloat16 l0 = __float2bfloat16(v.x - __bfloat162float(h0));
    __nv_bfloat16 l1 = __float2bfloat16(v.y - __bfloat162float(h1));
    __nv_bfloat16 l2 = __float2bfloat16(v.z - __bfloat162float(h2));
    __nv_bfloat16 l3 = __float2bfloat16(v.w - __bfloat162float(h3));
    __nv_bfloat162 hp0(h0, h1), hp1(h2, h3), lp0(l0, l1), lp1(l2, l3);
    uint2 hv, lv;
    hv.x = *(uint32_t*)&hp0; hv.y = *(uint32_t*)&hp1;
    lv.x = *(uint32_t*)&lp0; lv.y = *(uint32_t*)&lp1;
    ((uint2*)hi)[i] = hv;
    ((uint2*)lo)[i] = lv;
}

// ---------------- mma.sync split-bf16 GEMM ----------------------------------
// C[M,N] = A[M,512]*B[N,512]^T, A=Ahi+Alo, B=Bhi+Blo (3 HMMA products).
// CTA 128x128, 256 thr (warps 2x4, each 64x32). BK=32, double-buffered cp.async.
// smem row pitch 80B (32 bf16 + 8B pad) -> conflict-free 32-bit fragment loads.
// REMAP: A row r -> (r/32)*128 + r%32.  FINAL: +bias, zero rows with rowmask!=0.
#define PITCH 80
#define MATB  (128 * PITCH)       // 10240 bytes per matrix buffer
#define STAGEB (4 * MATB)         // Ah|Al|Bh|Bl per stage

template<bool REMAP, bool FINAL>
__global__ __launch_bounds__(256)
void gemm_mma(const __nv_bfloat16* __restrict__ Ahi, const __nv_bfloat16* __restrict__ Alo,
              const __nv_bfloat16* __restrict__ Bhi, const __nv_bfloat16* __restrict__ Blo,
              float* __restrict__ C, int ldc,
              const float* __restrict__ bias, const int* __restrict__ rowmask)
{
    extern __shared__ char sm[];
    const int tid  = threadIdx.x;
    const int wid  = tid >> 5, lane = tid & 31;
    const int wm   = wid >> 2, wn = wid & 3;          // warp grid 2x4
    const int tm   = blockIdx.y, tn = blockIdx.x;
    const int lr4  = lane >> 2;                        // 0..7
    const int lc   = lane & 3;                         // 0..3

    // global-load task mapping: 512 chunks of 16B per matrix per stage
    const int gr  = tid >> 1;            // 0..127 row within tile
    const int gc  = (tid & 1) << 1;      // chunk pair start 0 or 2

    int arow = tm * 128 + gr;
    if (REMAP) arow = ((arow >> 5) << 7) | (arow & 31);
    const __nv_bfloat16* gAh = Ahi + (size_t)arow * KDIM + gc * 8;
    const __nv_bfloat16* gAl = Alo + (size_t)arow * KDIM + gc * 8;
    const __nv_bfloat16* gBh = Bhi + (size_t)(tn * 128 + gr) * KDIM + gc * 8;
    const __nv_bfloat16* gBl = Blo + (size_t)(tn * 128 + gr) * KDIM + gc * 8;
    const uint32_t smb = smem_u32(sm);
    const uint32_t dst0 = smb + gr * PITCH + gc * 16;

    float acc[4][4][4];
    #pragma unroll
    for (int i = 0; i < 4; i++)
        #pragma unroll
        for (int j = 0; j < 4; j++)
            #pragma unroll
            for (int k = 0; k < 4; k++) acc[i][j][k] = 0.f;

    // issue loads for chunk `ch` into stage buffer st
    auto issue = [&](int ch, int st) {
        const int koff = ch * 32;                         // bf16 elements
        const uint32_t d = dst0 + st * STAGEB;
        #pragma unroll
        for (int c = 0; c < 2; c++) {
            CP16(d + 0*MATB + c*16, gAh + koff + c*8);
            CP16(d + 1*MATB + c*16, gAl + koff + c*8);
            CP16(d + 2*MATB + c*16, gBh + koff + c*8);
            CP16(d + 3*MATB + c*16, gBl + koff + c*8);
        }
        CP_COMMIT();
    };

    issue(0, 0);

    const char* base = sm;
    const int warpRow = wm * 64;
    const int warpCol = wn * 32;

    for (int ch = 0; ch < 16; ch++) {
        const int st = ch & 1;
        if (ch < 15) { issue(ch + 1, st ^ 1); CP_WAIT(1); }
        else         { CP_WAIT(0); }
        __syncthreads();

        const char* sAh = base + st * STAGEB + 0*MATB;
        const char* sAl = base + st * STAGEB + 1*MATB;
        const char* sBh = base + st * STAGEB + 2*MATB;
        const char* sBl = base + st * STAGEB + 3*MATB;

        #pragma unroll
        for (int ks = 0; ks < 2; ks++) {
            const int kb = (lc * 2 + ks * 16) * 2;        // byte offset of k pair
            uint32_t ah[4][4], al[4][4], bh[4][2], bl[4][2];
            #pragma unroll
            for (int mt = 0; mt < 4; mt++) {
                int r = warpRow + mt * 16 + lr4;
                const char* p0 = sAh + r * PITCH + kb;
                const char* p1 = sAh + (r + 8) * PITCH + kb;
                ah[mt][0] = *(const uint32_t*)p0;
                ah[mt][1] = *(const uint32_t*)p1;
                ah[mt][2] = *(const uint32_t*)(p0 + 16);
                ah[mt][3] = *(const uint32_t*)(p1 + 16);
                const char* q0 = sAl + r * PITCH + kb;
                const char* q1 = sAl + (r + 8) * PITCH + kb;
                al[mt][0] = *(const uint32_t*)q0;
                al[mt][1] = *(const uint32_t*)q1;
                al[mt][2] = *(const uint32_t*)(q0 + 16);
                al[mt][3] = *(const uint32_t*)(q1 + 16);
            }
            #pragma unroll
            for (int nt = 0; nt < 4; nt++) {
                int cidx = warpCol + nt * 8 + lr4;
                const char* p = sBh + cidx * PITCH + kb;
                bh[nt][0] = *(const uint32_t*)p;
                bh[nt][1] = *(const uint32_t*)(p + 16);
                const char* q = sBl + cidx * PITCH + kb;
                bl[nt][0] = *(const uint32_t*)q;
                bl[nt][1] = *(const uint32_t*)(q + 16);
            }
            #pragma unroll
            for (int mt = 0; mt < 4; mt++)
                #pragma unroll
                for (int nt = 0; nt < 4; nt++) {
                    mma_bf16(acc[mt][nt], ah[mt], bh[nt]);
                    mma_bf16(acc[mt][nt], ah[mt], bl[nt]);
                    mma_bf16(acc[mt][nt], al[mt], bh[nt]);
                }
        }
        __syncthreads();
    }

    // epilogue: each thread owns float2 pairs at (r, c) and (r+8, c)
    #pragma unroll
    for (int mt = 0; mt < 4; mt++) {
        int r0 = tm * 128 + warpRow + mt * 16 + lr4;
        int r1 = r0 + 8;
        bool z0 = false, z1 = false;
        if (FINAL) { z0 = rowmask[r0] != 0; z1 = rowmask[r1] != 0; }
        #pragma unroll
        for (int nt = 0; nt < 4; nt++) {
            int c = tn * 128 + warpCol + nt * 8 + lc * 2;
            float2 v0 = make_float2(acc[mt][nt][0], acc[mt][nt][1]);
            float2 v1 = make_float2(acc[mt][nt][2], acc[mt][nt][3]);
            if (FINAL) {
                float2 bb = *(const float2*)(bias + c);
                if (z0) v0 = make_float2(0.f, 0.f);
                else    { v0.x += bb.x; v0.y += bb.y; }
                if (z1) v1 = make_float2(0.f, 0.f);
                else    { v1.x += bb.x; v1.y += bb.y; }
            }
            *(float2*)(C + (size_t)r0 * ldc + c) = v0;
            *(float2*)(C + (size_t)r1 * ldc + c) = v1;
        }
    }
}

// ---------------- fused attention (fp32, unchanged) -------------------------
__global__ __launch_bounds__(256)
void attn_kernel(const float* __restrict__ q, const float* __restrict__ kv,
                 const int* __restrict__ pre_mask, float* __restrict__ out)
{
    __shared__ float smA[4096];
    __shared__ float smB[8192];
    const int tid = threadIdx.x;
    const int b = blockIdx.x >> 3;
    const int h = blockIdx.x & 7;

    const float* qbase = q  + (size_t)b * (NAG * EMB) + h * HDD;
    const float* kbase = kv + (size_t)b * (NE_ * 1024) + h * HDD;
    const float* vbase = kbase + EMB;

    {
        int i = tid;
        #pragma unroll
        for (int it = 0; it < 2; it++, i += 256) {
            int a = i >> 4, d4 = (i & 15) << 2;
            float4 v = *(const float4*)(qbase + (size_t)a * EMB + d4);
            smA[(d4+0)*32 + a] = v.x; smA[(d4+1)*32 + a] = v.y;
            smA[(d4+2)*32 + a] = v.z; smA[(d4+3)*32 + a] = v.w;
        }
    }
    {
        int i = tid;
        #pragma unroll
        for (int it = 0; it < 8; it++, i += 256) {
            int e = i >> 4, d4 = (i & 15) << 2;
            float4 v = *(const float4*)(kbase + (size_t)e * 1024 + d4);
            smB[(d4+0)*128 + e] = v.x; smB[(d4+1)*128 + e] = v.y;
            smB[(d4+2)*128 + e] = v.z; smB[(d4+3)*128 + e] = v.w;
        }
    }
    __syncthreads();

    const int e0 = (tid & 31) << 2;
    const int a0 = (tid >> 5) << 2;
    float lg[4][4];
    #pragma unroll
    for (int i = 0; i < 4; i++)
        #pragma unroll
        for (int j = 0; j < 4; j++) lg[i][j] = 0.f;

    #pragma unroll 8
    for (int d = 0; d < 64; d++) {
        float4 qa = *(const float4*)&smA[d*32  + a0];
        float4 kb = *(const float4*)&smB[d*128 + e0];
        float qv[4] = {qa.x, qa.y, qa.z, qa.w};
        float kk[4] = {kb.x, kb.y, kb.z, kb.w};
        #pragma unroll
        for (int i = 0; i < 4; i++)
            #pragma unroll
            for (int j = 0; j < 4; j++)
                lg[i][j] = fmaf(qv[i], kk[j], lg[i][j]);
    }
    __syncthreads();

    const int* mbase = pre_mask + (size_t)b * (NAG * NE_);
    #pragma unroll
    for (int i = 0; i < 4; i++) {
        int a = a0 + i;
        int4 m = *(const int4*)(mbase + a * NE_ + e0);
        float* lrow = &smA[a * 128 + e0];
        lrow[0] = m.x ? -1e30f : lg[i][0] * 0.125f;
        lrow[1] = m.y ? -1e30f : lg[i][1] * 0.125f;
        lrow[2] = m.z ? -1e30f : lg[i][2] * 0.125f;
        lrow[3] = m.w ? -1e30f : lg[i][3] * 0.125f;
    }
    {
        int i = tid;
        #pragma unroll
        for (int it = 0; it < 8; it++, i += 256) {
            int e = i >> 4, d4 = (i & 15) << 2;
            *(float4*)&smB[e*64 + d4] = *(const float4*)(vbase + (size_t)e * 1024 + d4);
        }
    }
    __syncthreads();

    {
        int a = tid >> 3, l = tid & 7;
        float* row = &smA[a * 128];
        float mx = -1e30f;
        #pragma unroll
        for (int j = 0; j < 16; j++) mx = fmaxf(mx, row[l + 8*j]);
        mx = fmaxf(mx, __shfl_xor_sync(0xffffffffu, mx, 1));
        mx = fmaxf(mx, __shfl_xor_sync(0xffffffffu, mx, 2));
        mx = fmaxf(mx, __shfl_xor_sync(0xffffffffu, mx, 4));
        float ex[16], sum = 0.f;
        #pragma unroll
        for (int j = 0; j < 16; j++) { float t = __expf(row[l + 8*j] - mx); ex[j] = t; sum += t; }
        sum += __shfl_xor_sync(0xffffffffu, sum, 1);
        sum += __shfl_xor_sync(0xffffffffu, sum, 2);
        sum += __shfl_xor_sync(0xffffffffu, sum, 4);
        float inv = (mx <= -1e29f) ? 0.f : (1.0f / sum);
        #pragma unroll
        for (int j = 0; j < 16; j++) row[l + 8*j] = ex[j] * inv;
    }
    __syncthreads();

    const int d0 = (tid & 31) << 1;
    const int a1 = (tid >> 5) << 2;
    float oa[4][2];
    #pragma unroll
    for (int i = 0; i < 4; i++) { oa[i][0] = 0.f; oa[i][1] = 0.f; }

    #pragma unroll 8
    for (int e = 0; e < 128; e++) {
        float2 vv = *(const float2*)&smB[e*64 + d0];
        #pragma unroll
        for (int i = 0; i < 4; i++) {
            float w = smA[(a1 + i) * 128 + e];
            oa[i][0] = fmaf(w, vv.x, oa[i][0]);
            oa[i][1] = fmaf(w, vv.y, oa[i][1]);
        }
    }
    float* obase = out + (size_t)b * (NAG * EMB) + h * HDD;
    #pragma unroll
    for (int i = 0; i < 4; i++)
        *(float2*)(obase + (size_t)(a1 + i) * EMB + d0) = make_float2(oa[i][0], oa[i][1]);
}

// ---------------- launch ---------------------------------------------------
extern "C" void kernel_launch(void* const* d_in, const int* in_sizes, int n_in,
                              void* d_out, int out_size)
{
    const float* entities  = (const float*)d_in[0];
    const int*   pre_mask  = (const int*)d_in[1];
    const int*   post_mask = (const int*)d_in[2];
    const float* W_in      = (const float*)d_in[3];
    const float* W_out     = (const float*)d_in[4];
    const float* b_out     = (const float*)d_in[5];
    float*       out       = (float*)d_out;

    float *kv_p, *q_p, *at_p;
    __nv_bfloat16 *ehi, *elo, *wihi, *wilo, *wohi, *wolo, *athi, *atlo;
    cudaGetSymbolAddress((void**)&kv_p, g_kv);
    cudaGetSymbolAddress((void**)&q_p,  g_q);
    cudaGetSymbolAddress((void**)&at_p, g_at);
    cudaGetSymbolAddress((void**)&ehi,  g_ehi);
    cudaGetSymbolAddress((void**)&elo,  g_elo);
    cudaGetSymbolAddress((void**)&wihi, g_wihi);
    cudaGetSymbolAddress((void**)&wilo, g_wilo);
    cudaGetSymbolAddress((void**)&wohi, g_wohi);
    cudaGetSymbolAddress((void**)&wolo, g_wolo);
    cudaGetSymbolAddress((void**)&athi, g_athi);
    cudaGetSymbolAddress((void**)&atlo, g_atlo);

    const int SMEM_BYTES = 2 * STAGEB;   // 81920
    cudaFuncSetAttribute(gemm_mma<false,false>, cudaFuncAttributeMaxDynamicSharedMemorySize, SMEM_BYTES);
    cudaFuncSetAttribute(gemm_mma<true, false>, cudaFuncAttributeMaxDynamicSharedMemorySize, SMEM_BYTES);
    cudaFuncSetAttribute(gemm_mma<false,true >, cudaFuncAttributeMaxDynamicSharedMemorySize, SMEM_BYTES);

    // split inputs to bf16 hi/lo
    split_kernel<<<(BS_*NE_*KDIM/4 + 255)/256, 256>>>(entities, ehi, elo, BS_*NE_*KDIM/4);
    split_kernel<<<(3*EMB*KDIM/4   + 255)/256, 256>>>(W_in,  wihi, wilo, 3*EMB*KDIM/4);
    split_kernel<<<(EMB*EMB/4      + 255)/256, 256>>>(W_out, wohi, wolo, EMB*EMB/4);

    // K|V projection: [131072,512] x W_in[512:1536]^T -> g_kv [131072,1024]
    gemm_mma<false,false><<<dim3(8, 1024), 256, SMEM_BYTES>>>(
        ehi, elo, wihi + 512*512, wilo + 512*512, kv_p, 1024, nullptr, nullptr);

    // Q projection (agent rows): [32768,512] x W_in[0:512]^T -> g_q
    gemm_mma<true,false><<<dim3(4, 256), 256, SMEM_BYTES>>>(
        ehi, elo, wihi, wilo, q_p, 512, nullptr, nullptr);

    // attention
    attn_kernel<<<BS_ * NHD, 256>>>(q_p, kv_p, pre_mask, at_p);

    // split attention output, then out GEMM + bias + post-mask
    split_kernel<<<(BS_*NAG*EMB/4 + 255)/256, 256>>>(at_p, athi, atlo, BS_*NAG*EMB/4);
    gemm_mma<false,true><<<dim3(4, 256), 256, SMEM_BYTES>>>(
        athi, atlo, wohi, wolo, out, 512, b_out, post_mask);
}

// round 5
// speedup vs baseline: 1.9558x; 1.0660x over previous
#include <cuda_runtime.h>
#include <cstdint>

#define BS_   1024
#define NE_   128
#define EMB   512
#define NAG   32
#define NHD   8
#define HDD   64
#define KDIM  512

// ---------------- scratch (device globals; allocation-guard safe) ----------
__device__ float g_kv[(size_t)BS_ * NE_ * 1024];   // [b*128+e][K(512)|V(512)]
__device__ float g_q [(size_t)BS_ * NAG * EMB];
__device__ float g_at[(size_t)BS_ * NAG * EMB];

// ---------------- helpers ----------------------------------------------------
#define CP16(dst, src) \
    asm volatile("cp.async.cg.shared.global [%0], [%1], 16;" :: "r"(dst), "l"(src) : "memory")
#define CP_COMMIT()  asm volatile("cp.async.commit_group;" ::: "memory")
#define CP_WAIT(n)   asm volatile("cp.async.wait_group %0;" :: "n"(n) : "memory")

__device__ __forceinline__ uint32_t smem_u32(const void* p) {
    uint32_t a;
    asm("{ .reg .u64 t; cvta.to.shared.u64 t, %1; cvt.u32.u64 %0, t; }" : "=r"(a) : "l"(p));
    return a;
}
__device__ __forceinline__ uint32_t f2tf32(float f) {
    uint32_t r;
    asm("cvt.rna.tf32.f32 %0, %1;" : "=r"(r) : "f"(f));
    return r;
}
__device__ __forceinline__ void mma_tf32(float* c, const uint32_t* a, const uint32_t* b) {
    asm volatile(
        "mma.sync.aligned.m16n8k8.row.col.f32.tf32.tf32.f32 "
        "{%0,%1,%2,%3}, {%4,%5,%6,%7}, {%8,%9}, {%0,%1,%2,%3};"
        : "+f"(c[0]), "+f"(c[1]), "+f"(c[2]), "+f"(c[3])
        : "r"(a[0]), "r"(a[1]), "r"(a[2]), "r"(a[3]), "r"(b[0]), "r"(b[1]));
}

// ---------------- TF32 mma.sync GEMM ----------------------------------------
// C[M,N] = A[M,512] * B[N,512]^T, fp32 in / tf32 MMA / fp32 acc.
// CTA 128x128, 256 thr (warps 2x4, each 64x32). BK=32, 3-stage cp.async ring.
// smem row pitch 36 floats (144B) -> conflict-free 32-bit fragment loads.
// REMAP: A row r -> (r/32)*128 + r%32.  FINAL: +bias, zero rows with rowmask!=0.
#define FPITCH 36
#define ROWB   (FPITCH * 4)            // 144 bytes
#define MATB   (128 * ROWB)            // 18432 bytes per matrix
#define STAGEB (2 * MATB)              // A|B per stage
#define NSTAGE 3

template<bool REMAP, bool FINAL>
__global__ __launch_bounds__(256, 2)
void gemm_tf32(const float* __restrict__ A, const float* __restrict__ B,
               float* __restrict__ C, int ldc,
               const float* __restrict__ bias, const int* __restrict__ rowmask)
{
    extern __shared__ char sm[];
    const int tid  = threadIdx.x;
    const int wid  = tid >> 5, lane = tid & 31;
    const int wm   = wid >> 2, wn = wid & 3;          // warp grid 2x4
    const int tm   = blockIdx.y, tn = blockIdx.x;
    const int lr4  = lane >> 2;                        // 0..7
    const int lc   = lane & 3;                         // 0..3

    // global-load mapping: 2 threads per row, 64B (4x16B) each per matrix
    const int gr = tid >> 1;             // row 0..127
    const int gh = (tid & 1) << 4;       // half-row float offset: 0 or 16

    int arow = tm * 128 + gr;
    if (REMAP) arow = ((arow >> 5) << 7) | (arow & 31);
    const float* gA = A + (size_t)arow * KDIM + gh;
    const float* gB = B + (size_t)(tn * 128 + gr) * KDIM + gh;
    const uint32_t smb  = smem_u32(sm);
    const uint32_t dst0 = smb + gr * ROWB + gh * 4;

    float acc[4][4][4];
    #pragma unroll
    for (int i = 0; i < 4; i++)
        #pragma unroll
        for (int j = 0; j < 4; j++)
            #pragma unroll
            for (int k = 0; k < 4; k++) acc[i][j][k] = 0.f;

    auto issue = [&](int ch, int st) {
        const int koff = ch * 32;
        const uint32_t d = dst0 + st * STAGEB;
        #pragma unroll
        for (int c = 0; c < 4; c++) {
            CP16(d + c*16,        gA + koff + c*4);
            CP16(d + MATB + c*16, gB + koff + c*4);
        }
        CP_COMMIT();
    };

    issue(0, 0);
    issue(1, 1);

    const int warpRow = wm * 64;
    const int warpCol = wn * 32;

    for (int ch = 0; ch < 16; ch++) {
        if (ch < 15) CP_WAIT(1); else CP_WAIT(0);
        __syncthreads();
        if (ch + 2 < 16) {
            int st2 = (ch + 2) % NSTAGE;
            issue(ch + 2, st2);
        }
        const int st = ch % NSTAGE;
        const char* sA = sm + st * STAGEB;
        const char* sB = sA + MATB;

        #pragma unroll
        for (int ks = 0; ks < 4; ks++) {
            const int kb = ks * 32 + lc * 4;           // byte offset in row
            uint32_t af[4][4], bf[4][2];
            #pragma unroll
            for (int mt = 0; mt < 4; mt++) {
                int r = warpRow + mt * 16 + lr4;
                const char* p0 = sA + r * ROWB + kb;
                const char* p1 = sA + (r + 8) * ROWB + kb;
                af[mt][0] = f2tf32(*(const float*)p0);
                af[mt][1] = f2tf32(*(const float*)p1);
                af[mt][2] = f2tf32(*(const float*)(p0 + 16));
                af[mt][3] = f2tf32(*(const float*)(p1 + 16));
            }
            #pragma unroll
            for (int nt = 0; nt < 4; nt++) {
                int cidx = warpCol + nt * 8 + lr4;
                const char* p = sB + cidx * ROWB + kb;
                bf[nt][0] = f2tf32(*(const float*)p);
                bf[nt][1] = f2tf32(*(const float*)(p + 16));
            }
            #pragma unroll
            for (int mt = 0; mt < 4; mt++)
                #pragma unroll
                for (int nt = 0; nt < 4; nt++)
                    mma_tf32(acc[mt][nt], af[mt], bf[nt]);
        }
        __syncthreads();
    }

    // epilogue: each thread owns float2 pairs at (r, c) and (r+8, c)
    #pragma unroll
    for (int mt = 0; mt < 4; mt++) {
        int r0 = tm * 128 + warpRow + mt * 16 + lr4;
        int r1 = r0 + 8;
        bool z0 = false, z1 = false;
        if (FINAL) { z0 = rowmask[r0] != 0; z1 = rowmask[r1] != 0; }
        #pragma unroll
        for (int nt = 0; nt < 4; nt++) {
            int c = tn * 128 + warpCol + nt * 8 + lc * 2;
            float2 v0 = make_float2(acc[mt][nt][0], acc[mt][nt][1]);
            float2 v1 = make_float2(acc[mt][nt][2], acc[mt][nt][3]);
            if (FINAL) {
                float2 bb = *(const float2*)(bias + c);
                if (z0) v0 = make_float2(0.f, 0.f);
                else    { v0.x += bb.x; v0.y += bb.y; }
                if (z1) v1 = make_float2(0.f, 0.f);
                else    { v1.x += bb.x; v1.y += bb.y; }
            }
            *(float2*)(C + (size_t)r0 * ldc + c) = v0;
            *(float2*)(C + (size_t)r1 * ldc + c) = v1;
        }
    }
}

// ---------------- fused attention (fp32, unchanged) -------------------------
__global__ __launch_bounds__(256)
void attn_kernel(const float* __restrict__ q, const float* __restrict__ kv,
                 const int* __restrict__ pre_mask, float* __restrict__ out)
{
    __shared__ float smA[4096];
    __shared__ float smB[8192];
    const int tid = threadIdx.x;
    const int b = blockIdx.x >> 3;
    const int h = blockIdx.x & 7;

    const float* qbase = q  + (size_t)b * (NAG * EMB) + h * HDD;
    const float* kbase = kv + (size_t)b * (NE_ * 1024) + h * HDD;
    const float* vbase = kbase + EMB;

    {
        int i = tid;
        #pragma unroll
        for (int it = 0; it < 2; it++, i += 256) {
            int a = i >> 4, d4 = (i & 15) << 2;
            float4 v = *(const float4*)(qbase + (size_t)a * EMB + d4);
            smA[(d4+0)*32 + a] = v.x; smA[(d4+1)*32 + a] = v.y;
            smA[(d4+2)*32 + a] = v.z; smA[(d4+3)*32 + a] = v.w;
        }
    }
    {
        int i = tid;
        #pragma unroll
        for (int it = 0; it < 8; it++, i += 256) {
            int e = i >> 4, d4 = (i & 15) << 2;
            float4 v = *(const float4*)(kbase + (size_t)e * 1024 + d4);
            smB[(d4+0)*128 + e] = v.x; smB[(d4+1)*128 + e] = v.y;
            smB[(d4+2)*128 + e] = v.z; smB[(d4+3)*128 + e] = v.w;
        }
    }
    __syncthreads();

    const int e0 = (tid & 31) << 2;
    const int a0 = (tid >> 5) << 2;
    float lg[4][4];
    #pragma unroll
    for (int i = 0; i < 4; i++)
        #pragma unroll
        for (int j = 0; j < 4; j++) lg[i][j] = 0.f;

    #pragma unroll 8
    for (int d = 0; d < 64; d++) {
        float4 qa = *(const float4*)&smA[d*32  + a0];
        float4 kb = *(const float4*)&smB[d*128 + e0];
        float qv[4] = {qa.x, qa.y, qa.z, qa.w};
        float kk[4] = {kb.x, kb.y, kb.z, kb.w};
        #pragma unroll
        for (int i = 0; i < 4; i++)
            #pragma unroll
            for (int j = 0; j < 4; j++)
                lg[i][j] = fmaf(qv[i], kk[j], lg[i][j]);
    }
    __syncthreads();

    const int* mbase = pre_mask + (size_t)b * (NAG * NE_);
    #pragma unroll
    for (int i = 0; i < 4; i++) {
        int a = a0 + i;
        int4 m = *(const int4*)(mbase + a * NE_ + e0);
        float* lrow = &smA[a * 128 + e0];
        lrow[0] = m.x ? -1e30f : lg[i][0] * 0.125f;
        lrow[1] = m.y ? -1e30f : lg[i][1] * 0.125f;
        lrow[2] = m.z ? -1e30f : lg[i][2] * 0.125f;
        lrow[3] = m.w ? -1e30f : lg[i][3] * 0.125f;
    }
    {
        int i = tid;
        #pragma unroll
        for (int it = 0; it < 8; it++, i += 256) {
            int e = i >> 4, d4 = (i & 15) << 2;
            *(float4*)&smB[e*64 + d4] = *(const float4*)(vbase + (size_t)e * 1024 + d4);
        }
    }
    __syncthreads();

    {
        int a = tid >> 3, l = tid & 7;
        float* row = &smA[a * 128];
        float mx = -1e30f;
        #pragma unroll
        for (int j = 0; j < 16; j++) mx = fmaxf(mx, row[l + 8*j]);
        mx = fmaxf(mx, __shfl_xor_sync(0xffffffffu, mx, 1));
        mx = fmaxf(mx, __shfl_xor_sync(0xffffffffu, mx, 2));
        mx = fmaxf(mx, __shfl_xor_sync(0xffffffffu, mx, 4));
        float ex[16], sum = 0.f;
        #pragma unroll
        for (int j = 0; j < 16; j++) { float t = __expf(row[l + 8*j] - mx); ex[j] = t; sum += t; }
        sum += __shfl_xor_sync(0xffffffffu, sum, 1);
        sum += __shfl_xor_sync(0xffffffffu, sum, 2);
        sum += __shfl_xor_sync(0xffffffffu, sum, 4);
        float inv = (mx <= -1e29f) ? 0.f : (1.0f / sum);
        #pragma unroll
        for (int j = 0; j < 16; j++) row[l + 8*j] = ex[j] * inv;
    }
    __syncthreads();

    const int d0 = (tid & 31) << 1;
    const int a1 = (tid >> 5) << 2;
    float oa[4][2];
    #pragma unroll
    for (int i = 0; i < 4; i++) { oa[i][0] = 0.f; oa[i][1] = 0.f; }

    #pragma unroll 8
    for (int e = 0; e < 128; e++) {
        float2 vv = *(const float2*)&smB[e*64 + d0];
        #pragma unroll
        for (int i = 0; i < 4; i++) {
            float w = smA[(a1 + i) * 128 + e];
            oa[i][0] = fmaf(w, vv.x, oa[i][0]);
            oa[i][1] = fmaf(w, vv.y, oa[i][1]);
        }
    }
    float* obase = out + (size_t)b * (NAG * EMB) + h * HDD;
    #pragma unroll
    for (int i = 0; i < 4; i++)
        *(float2*)(obase + (size_t)(a1 + i) * EMB + d0) = make_float2(oa[i][0], oa[i][1]);
}

// ---------------- launch ---------------------------------------------------
extern "C" void kernel_launch(void* const* d_in, const int* in_sizes, int n_in,
                              void* d_out, int out_size)
{
    const float* entities  = (const float*)d_in[0];
    const int*   pre_mask  = (const int*)d_in[1];
    const int*   post_mask = (const int*)d_in[2];
    const float* W_in      = (const float*)d_in[3];
    const float* W_out     = (const float*)d_in[4];
    const float* b_out     = (const float*)d_in[5];
    float*       out       = (float*)d_out;

    float *kv_p, *q_p, *at_p;
    cudaGetSymbolAddress((void**)&kv_p, g_kv);
    cudaGetSymbolAddress((void**)&q_p,  g_q);
    cudaGetSymbolAddress((void**)&at_p, g_at);

    const int SMEM_BYTES = NSTAGE * STAGEB;   // 110592
    cudaFuncSetAttribute(gemm_tf32<false,false>, cudaFuncAttributeMaxDynamicSharedMemorySize, SMEM_BYTES);
    cudaFuncSetAttribute(gemm_tf32<true, false>, cudaFuncAttributeMaxDynamicSharedMemorySize, SMEM_BYTES);
    cudaFuncSetAttribute(gemm_tf32<false,true >, cudaFuncAttributeMaxDynamicSharedMemorySize, SMEM_BYTES);

    // K|V projection: [131072,512] x W_in[512:1536]^T -> g_kv [131072,1024]
    gemm_tf32<false,false><<<dim3(8, 1024), 256, SMEM_BYTES>>>(
        entities, W_in + 512*512, kv_p, 1024, nullptr, nullptr);

    // Q projection (agent rows): [32768,512] x W_in[0:512]^T -> g_q
    gemm_tf32<true,false><<<dim3(4, 256), 256, SMEM_BYTES>>>(
        entities, W_in, q_p, 512, nullptr, nullptr);

    // attention
    attn_kernel<<<BS_ * NHD, 256>>>(q_p, kv_p, pre_mask, at_p);

    // out GEMM + bias + post-mask: [32768,512] x W_out^T
    gemm_tf32<false,true><<<dim3(4, 256), 256, SMEM_BYTES>>>(
        at_p, W_out, out, 512, b_out, post_mask);
}

// round 6
// speedup vs baseline: 1.9820x; 1.0134x over previous
#include <cuda_runtime.h>
#include <cstdint>

#define BS_   1024
#define NE_   128
#define EMB   512
#define NAG   32
#define NHD   8
#define HDD   64
#define KDIM  512

// ---------------- scratch (device globals; allocation-guard safe) ----------
__device__ float g_kv[(size_t)BS_ * NE_ * 1024];   // [b*128+e][K(512)|V(512)]
__device__ float g_q [(size_t)BS_ * NAG * EMB];
__device__ float g_at[(size_t)BS_ * NAG * EMB];    // attention out (tf32-rounded)
__device__ float g_er[(size_t)BS_ * NE_ * KDIM];   // entities, tf32-rounded
__device__ float g_wr[3 * EMB * KDIM];             // W_in, tf32-rounded
__device__ float g_wor[EMB * EMB];                 // W_out, tf32-rounded

// ---------------- helpers ----------------------------------------------------
#define CP16(dst, src) \
    asm volatile("cp.async.cg.shared.global [%0], [%1], 16;" :: "r"(dst), "l"(src) : "memory")
#define CP_COMMIT()  asm volatile("cp.async.commit_group;" ::: "memory")
#define CP_WAIT(n)   asm volatile("cp.async.wait_group %0;" :: "n"(n) : "memory")

__device__ __forceinline__ uint32_t smem_u32(const void* p) {
    uint32_t a;
    asm("{ .reg .u64 t; cvta.to.shared.u64 t, %1; cvt.u32.u64 %0, t; }" : "=r"(a) : "l"(p));
    return a;
}
__device__ __forceinline__ float f2tf32f(float f) {
    uint32_t r;
    asm("cvt.rna.tf32.f32 %0, %1;" : "=r"(r) : "f"(f));
    return __uint_as_float(r);
}
__device__ __forceinline__ void mma_tf32(float* c, const uint32_t* a, const uint32_t* b) {
    asm volatile(
        "mma.sync.aligned.m16n8k8.row.col.f32.tf32.tf32.f32 "
        "{%0,%1,%2,%3}, {%4,%5,%6,%7}, {%8,%9}, {%0,%1,%2,%3};"
        : "+f"(c[0]), "+f"(c[1]), "+f"(c[2]), "+f"(c[3])
        : "r"(a[0]), "r"(a[1]), "r"(a[2]), "r"(a[3]), "r"(b[0]), "r"(b[1]));
}

// ---------------- tf32 rounding pre-pass ------------------------------------
__global__ __launch_bounds__(256)
void round_tf32(const float* __restrict__ x, float* __restrict__ y, int n4)
{
    int i = blockIdx.x * 256 + threadIdx.x;
    if (i >= n4) return;
    float4 v = ((const float4*)x)[i];
    v.x = f2tf32f(v.x); v.y = f2tf32f(v.y);
    v.z = f2tf32f(v.z); v.w = f2tf32f(v.w);
    ((float4*)y)[i] = v;
}

// ---------------- TF32 mma.sync GEMM ----------------------------------------
// C[M,N] = A[M,512] * B[N,512]^T; inputs pre-rounded to tf32 bit patterns.
// CTA 128x128, 256 thr (warps 2x4, each 64x32). BK=32, 3-stage cp.async ring.
// smem row pitch 36 floats (144B) -> conflict-free 32-bit fragment loads.
// REMAP: A row r -> (r/32)*128 + r%32.  FINAL: +bias, zero rows with rowmask!=0.
#define FPITCH 36
#define ROWB   (FPITCH * 4)            // 144 bytes
#define MATB   (128 * ROWB)            // 18432 bytes per matrix
#define STAGEB (2 * MATB)              // A|B per stage
#define NSTAGE 3

template<bool REMAP, bool FINAL>
__global__ __launch_bounds__(256, 2)
void gemm_tf32(const float* __restrict__ A, const float* __restrict__ B,
               float* __restrict__ C, int ldc,
               const float* __restrict__ bias, const int* __restrict__ rowmask)
{
    extern __shared__ char sm[];
    const int tid  = threadIdx.x;
    const int wid  = tid >> 5, lane = tid & 31;
    const int wm   = wid >> 2, wn = wid & 3;          // warp grid 2x4
    const int tm   = blockIdx.y, tn = blockIdx.x;
    const int lr4  = lane >> 2;                        // 0..7
    const int lc   = lane & 3;                         // 0..3

    // global-load mapping: 2 threads per row, 64B (4x16B) each per matrix
    const int gr = tid >> 1;             // row 0..127
    const int gh = (tid & 1) << 4;       // half-row float offset: 0 or 16

    int arow = tm * 128 + gr;
    if (REMAP) arow = ((arow >> 5) << 7) | (arow & 31);
    const float* gA = A + (size_t)arow * KDIM + gh;
    const float* gB = B + (size_t)(tn * 128 + gr) * KDIM + gh;
    const uint32_t smb  = smem_u32(sm);
    const uint32_t dst0 = smb + gr * ROWB + gh * 4;

    float acc[4][4][4];
    #pragma unroll
    for (int i = 0; i < 4; i++)
        #pragma unroll
        for (int j = 0; j < 4; j++)
            #pragma unroll
            for (int k = 0; k < 4; k++) acc[i][j][k] = 0.f;

    auto issue = [&](int ch, int st) {
        const int koff = ch * 32;
        const uint32_t d = dst0 + st * STAGEB;
        #pragma unroll
        for (int c = 0; c < 4; c++) {
            CP16(d + c*16,        gA + koff + c*4);
            CP16(d + MATB + c*16, gB + koff + c*4);
        }
        CP_COMMIT();
    };

    issue(0, 0);
    issue(1, 1);

    const int warpRow = wm * 64;
    const int warpCol = wn * 32;

    for (int ch = 0; ch < 16; ch++) {
        if (ch < 15) CP_WAIT(1); else CP_WAIT(0);
        __syncthreads();
        if (ch + 2 < 16) {
            int st2 = (ch + 2) % NSTAGE;
            issue(ch + 2, st2);
        }
        const int st = ch % NSTAGE;
        const char* sA = sm + st * STAGEB;
        const char* sB = sA + MATB;

        #pragma unroll
        for (int ks = 0; ks < 4; ks++) {
            const int kb = ks * 32 + lc * 4;           // byte offset in row
            uint32_t af[4][4], bf[4][2];
            #pragma unroll
            for (int mt = 0; mt < 4; mt++) {
                int r = warpRow + mt * 16 + lr4;
                const char* p0 = sA + r * ROWB + kb;
                const char* p1 = sA + (r + 8) * ROWB + kb;
                af[mt][0] = *(const uint32_t*)p0;
                af[mt][1] = *(const uint32_t*)p1;
                af[mt][2] = *(const uint32_t*)(p0 + 16);
                af[mt][3] = *(const uint32_t*)(p1 + 16);
            }
            #pragma unroll
            for (int nt = 0; nt < 4; nt++) {
                int cidx = warpCol + nt * 8 + lr4;
                const char* p = sB + cidx * ROWB + kb;
                bf[nt][0] = *(const uint32_t*)p;
                bf[nt][1] = *(const uint32_t*)(p + 16);
            }
            #pragma unroll
            for (int mt = 0; mt < 4; mt++)
                #pragma unroll
                for (int nt = 0; nt < 4; nt++)
                    mma_tf32(acc[mt][nt], af[mt], bf[nt]);
        }
        __syncthreads();
    }

    // epilogue: each thread owns float2 pairs at (r, c) and (r+8, c)
    #pragma unroll
    for (int mt = 0; mt < 4; mt++) {
        int r0 = tm * 128 + warpRow + mt * 16 + lr4;
        int r1 = r0 + 8;
        bool z0 = false, z1 = false;
        if (FINAL) { z0 = rowmask[r0] != 0; z1 = rowmask[r1] != 0; }
        #pragma unroll
        for (int nt = 0; nt < 4; nt++) {
            int c = tn * 128 + warpCol + nt * 8 + lc * 2;
            float2 v0 = make_float2(acc[mt][nt][0], acc[mt][nt][1]);
            float2 v1 = make_float2(acc[mt][nt][2], acc[mt][nt][3]);
            if (FINAL) {
                float2 bb = *(const float2*)(bias + c);
                if (z0) v0 = make_float2(0.f, 0.f);
                else    { v0.x += bb.x; v0.y += bb.y; }
                if (z1) v1 = make_float2(0.f, 0.f);
                else    { v1.x += bb.x; v1.y += bb.y; }
            }
            *(float2*)(C + (size_t)r0 * ldc + c) = v0;
            *(float2*)(C + (size_t)r1 * ldc + c) = v1;
        }
    }
}

// ---------------- fused attention (fp32; output tf32-rounded) ---------------
__global__ __launch_bounds__(256)
void attn_kernel(const float* __restrict__ q, const float* __restrict__ kv,
                 const int* __restrict__ pre_mask, float* __restrict__ out)
{
    __shared__ float smA[4096];
    __shared__ float smB[8192];
    const int tid = threadIdx.x;
    const int b = blockIdx.x >> 3;
    const int h = blockIdx.x & 7;

    const float* qbase = q  + (size_t)b * (NAG * EMB) + h * HDD;
    const float* kbase = kv + (size_t)b * (NE_ * 1024) + h * HDD;
    const float* vbase = kbase + EMB;

    {
        int i = tid;
        #pragma unroll
        for (int it = 0; it < 2; it++, i += 256) {
            int a = i >> 4, d4 = (i & 15) << 2;
            float4 v = *(const float4*)(qbase + (size_t)a * EMB + d4);
            smA[(d4+0)*32 + a] = v.x; smA[(d4+1)*32 + a] = v.y;
            smA[(d4+2)*32 + a] = v.z; smA[(d4+3)*32 + a] = v.w;
        }
    }
    {
        int i = tid;
        #pragma unroll
        for (int it = 0; it < 8; it++, i += 256) {
            int e = i >> 4, d4 = (i & 15) << 2;
            float4 v = *(const float4*)(kbase + (size_t)e * 1024 + d4);
            smB[(d4+0)*128 + e] = v.x; smB[(d4+1)*128 + e] = v.y;
            smB[(d4+2)*128 + e] = v.z; smB[(d4+3)*128 + e] = v.w;
        }
    }
    __syncthreads();

    const int e0 = (tid & 31) << 2;
    const int a0 = (tid >> 5) << 2;
    float lg[4][4];
    #pragma unroll
    for (int i = 0; i < 4; i++)
        #pragma unroll
        for (int j = 0; j < 4; j++) lg[i][j] = 0.f;

    #pragma unroll 8
    for (int d = 0; d < 64; d++) {
        float4 qa = *(const float4*)&smA[d*32  + a0];
        float4 kb = *(const float4*)&smB[d*128 + e0];
        float qv[4] = {qa.x, qa.y, qa.z, qa.w};
        float kk[4] = {kb.x, kb.y, kb.z, kb.w};
        #pragma unroll
        for (int i = 0; i < 4; i++)
            #pragma unroll
            for (int j = 0; j < 4; j++)
                lg[i][j] = fmaf(qv[i], kk[j], lg[i][j]);
    }
    __syncthreads();

    const int* mbase = pre_mask + (size_t)b * (NAG * NE_);
    #pragma unroll
    for (int i = 0; i < 4; i++) {
        int a = a0 + i;
        int4 m = *(const int4*)(mbase + a * NE_ + e0);
        float* lrow = &smA[a * 128 + e0];
        lrow[0] = m.x ? -1e30f : lg[i][0] * 0.125f;
        lrow[1] = m.y ? -1e30f : lg[i][1] * 0.125f;
        lrow[2] = m.z ? -1e30f : lg[i][2] * 0.125f;
        lrow[3] = m.w ? -1e30f : lg[i][3] * 0.125f;
    }
    {
        int i = tid;
        #pragma unroll
        for (int it = 0; it < 8; it++, i += 256) {
            int e = i >> 4, d4 = (i & 15) << 2;
            *(float4*)&smB[e*64 + d4] = *(const float4*)(vbase + (size_t)e * 1024 + d4);
        }
    }
    __syncthreads();

    {
        int a = tid >> 3, l = tid & 7;
        float* row = &smA[a * 128];
        float mx = -1e30f;
        #pragma unroll
        for (int j = 0; j < 16; j++) mx = fmaxf(mx, row[l + 8*j]);
        mx = fmaxf(mx, __shfl_xor_sync(0xffffffffu, mx, 1));
        mx = fmaxf(mx, __shfl_xor_sync(0xffffffffu, mx, 2));
        mx = fmaxf(mx, __shfl_xor_sync(0xffffffffu, mx, 4));
        float ex[16], sum = 0.f;
        #pragma unroll
        for (int j = 0; j < 16; j++) { float t = __expf(row[l + 8*j] - mx); ex[j] = t; sum += t; }
        sum += __shfl_xor_sync(0xffffffffu, sum, 1);
        sum += __shfl_xor_sync(0xffffffffu, sum, 2);
        sum += __shfl_xor_sync(0xffffffffu, sum, 4);
        float inv = (mx <= -1e29f) ? 0.f : (1.0f / sum);
        #pragma unroll
        for (int j = 0; j < 16; j++) row[l + 8*j] = ex[j] * inv;
    }
    __syncthreads();

    const int d0 = (tid & 31) << 1;
    const int a1 = (tid >> 5) << 2;
    float oa[4][2];
    #pragma unroll
    for (int i = 0; i < 4; i++) { oa[i][0] = 0.f; oa[i][1] = 0.f; }

    #pragma unroll 8
    for (int e = 0; e < 128; e++) {
        float2 vv = *(const float2*)&smB[e*64 + d0];
        #pragma unroll
        for (int i = 0; i < 4; i++) {
            float w = smA[(a1 + i) * 128 + e];
            oa[i][0] = fmaf(w, vv.x, oa[i][0]);
            oa[i][1] = fmaf(w, vv.y, oa[i][1]);
        }
    }
    float* obase = out + (size_t)b * (NAG * EMB) + h * HDD;
    #pragma unroll
    for (int i = 0; i < 4; i++)
        *(float2*)(obase + (size_t)(a1 + i) * EMB + d0) =
            make_float2(f2tf32f(oa[i][0]), f2tf32f(oa[i][1]));   // pre-round for out-GEMM
}

// ---------------- launch ---------------------------------------------------
extern "C" void kernel_launch(void* const* d_in, const int* in_sizes, int n_in,
                              void* d_out, int out_size)
{
    const float* entities  = (const float*)d_in[0];
    const int*   pre_mask  = (const int*)d_in[1];
    const int*   post_mask = (const int*)d_in[2];
    const float* W_in      = (const float*)d_in[3];
    const float* W_out     = (const float*)d_in[4];
    const float* b_out     = (const float*)d_in[5];
    float*       out       = (float*)d_out;

    float *kv_p, *q_p, *at_p, *er_p, *wr_p, *wor_p;
    cudaGetSymbolAddress((void**)&kv_p,  g_kv);
    cudaGetSymbolAddress((void**)&q_p,   g_q);
    cudaGetSymbolAddress((void**)&at_p,  g_at);
    cudaGetSymbolAddress((void**)&er_p,  g_er);
    cudaGetSymbolAddress((void**)&wr_p,  g_wr);
    cudaGetSymbolAddress((void**)&wor_p, g_wor);

    const int SMEM_BYTES = NSTAGE * STAGEB;   // 110592
    cudaFuncSetAttribute(gemm_tf32<false,false>, cudaFuncAttributeMaxDynamicSharedMemorySize, SMEM_BYTES);
    cudaFuncSetAttribute(gemm_tf32<true, false>, cudaFuncAttributeMaxDynamicSharedMemorySize, SMEM_BYTES);
    cudaFuncSetAttribute(gemm_tf32<false,true >, cudaFuncAttributeMaxDynamicSharedMemorySize, SMEM_BYTES);

    // tf32 rounding pre-pass (entities + weights)
    round_tf32<<<(BS_*NE_*KDIM/4 + 255)/256, 256>>>(entities, er_p, BS_*NE_*KDIM/4);
    round_tf32<<<(3*EMB*KDIM/4   + 255)/256, 256>>>(W_in,  wr_p,  3*EMB*KDIM/4);
    round_tf32<<<(EMB*EMB/4      + 255)/256, 256>>>(W_out, wor_p, EMB*EMB/4);

    // K|V projection: [131072,512] x W_in[512:1536]^T -> g_kv [131072,1024]
    gemm_tf32<false,false><<<dim3(8, 1024), 256, SMEM_BYTES>>>(
        er_p, wr_p + 512*512, kv_p, 1024, nullptr, nullptr);

    // Q projection (agent rows): [32768,512] x W_in[0:512]^T -> g_q
    gemm_tf32<true,false><<<dim3(4, 256), 256, SMEM_BYTES>>>(
        er_p, wr_p, q_p, 512, nullptr, nullptr);

    // attention (writes tf32-rounded output)
    attn_kernel<<<BS_ * NHD, 256>>>(q_p, kv_p, pre_mask, at_p);

    // out GEMM + bias + post-mask: [32768,512] x W_out^T
    gemm_tf32<false,true><<<dim3(4, 256), 256, SMEM_BYTES>>>(
        at_p, wor_p, out, 512, b_out, post_mask);
}

// round 7
// speedup vs baseline: 2.3376x; 1.1794x over previous
#include <cuda_runtime.h>
#include <cstdint>

#define BS_   1024
#define NE_   128
#define EMB   512
#define NAG   32
#define NHD   8
#define HDD   64
#define KDIM  512

// ---------------- scratch (device globals; allocation-guard safe) ----------
__device__ float g_kv[(size_t)BS_ * NE_ * 1024];   // [b*128+e][K(512)|V(512)]
__device__ float g_q [(size_t)BS_ * NAG * EMB];
__device__ float g_at[(size_t)BS_ * NAG * EMB];    // attention out (tf32-rounded)
__device__ float g_er[(size_t)BS_ * NE_ * KDIM];   // entities, tf32-rounded
__device__ float g_wr[3 * EMB * KDIM];             // W_in, tf32-rounded
__device__ float g_wor[EMB * EMB];                 // W_out, tf32-rounded

// ---------------- helpers ----------------------------------------------------
#define CP16(dst, src) \
    asm volatile("cp.async.cg.shared.global [%0], [%1], 16;" :: "r"(dst), "l"(src) : "memory")
#define CP_COMMIT()  asm volatile("cp.async.commit_group;" ::: "memory")
#define CP_WAIT(n)   asm volatile("cp.async.wait_group %0;" :: "n"(n) : "memory")

__device__ __forceinline__ uint32_t smem_u32(const void* p) {
    uint32_t a;
    asm("{ .reg .u64 t; cvta.to.shared.u64 t, %1; cvt.u32.u64 %0, t; }" : "=r"(a) : "l"(p));
    return a;
}
__device__ __forceinline__ float f2tf32f(float f) {
    uint32_t r;
    asm("cvt.rna.tf32.f32 %0, %1;" : "=r"(r) : "f"(f));
    return __uint_as_float(r);
}
__device__ __forceinline__ void mma_tf32(float* c, const uint32_t* a, const uint32_t* b) {
    asm volatile(
        "mma.sync.aligned.m16n8k8.row.col.f32.tf32.tf32.f32 "
        "{%0,%1,%2,%3}, {%4,%5,%6,%7}, {%8,%9}, {%0,%1,%2,%3};"
        : "+f"(c[0]), "+f"(c[1]), "+f"(c[2]), "+f"(c[3])
        : "r"(a[0]), "r"(a[1]), "r"(a[2]), "r"(a[3]), "r"(b[0]), "r"(b[1]));
}

// ---------------- tf32 rounding pre-pass ------------------------------------
__global__ __launch_bounds__(256)
void round_tf32(const float* __restrict__ x, float* __restrict__ y, int n4)
{
    int i = blockIdx.x * 256 + threadIdx.x;
    if (i >= n4) return;
    float4 v = ((const float4*)x)[i];
    v.x = f2tf32f(v.x); v.y = f2tf32f(v.y);
    v.z = f2tf32f(v.z); v.w = f2tf32f(v.w);
    ((float4*)y)[i] = v;
}

// ---------------- TF32 mma.sync GEMM (warp tile 64x64) ----------------------
// C[M,N] = A[M,512] * B[N,512]^T; inputs pre-rounded to tf32 bit patterns.
// CTA 128x128, 128 thr (4 warps 2x2, each 64x64). BK=32, 3-stage cp.async ring,
// ONE barrier per chunk. smem pitch 36 floats -> conflict-free fragment LDS.
// REMAP: A row r -> (r/32)*128 + r%32.  FINAL: +bias, zero rows with rowmask!=0.
#define FPITCH 36
#define ROWB   (FPITCH * 4)            // 144 bytes
#define MATB   (128 * ROWB)            // 18432 bytes per matrix
#define STAGEB (2 * MATB)              // A|B per stage
#define NSTAGE 3

template<bool REMAP, bool FINAL>
__global__ __launch_bounds__(128, 2)
void gemm_tf32(const float* __restrict__ A, const float* __restrict__ B,
               float* __restrict__ C, int ldc,
               const float* __restrict__ bias, const int* __restrict__ rowmask)
{
    extern __shared__ char sm[];
    const int tid  = threadIdx.x;
    const int wid  = tid >> 5, lane = tid & 31;
    const int wm   = wid >> 1, wn = wid & 1;          // warp grid 2x2
    const int tm   = blockIdx.y, tn = blockIdx.x;
    const int lr4  = lane >> 2;                        // 0..7
    const int lc   = lane & 3;                         // 0..3

    // global-load mapping: 4 threads per row (16B each), rows rq+32k
    const int rq = tid >> 2;             // 0..31
    const int qo = (tid & 3) << 2;       // float offset 0,4,8,12

    const float* gA[4];
    const float* gB[4];
    #pragma unroll
    for (int k = 0; k < 4; k++) {
        int r = rq + 32 * k;
        int arow = tm * 128 + r;
        if (REMAP) arow = ((arow >> 5) << 7) | (arow & 31);
        gA[k] = A + (size_t)arow * KDIM + qo;
        gB[k] = B + (size_t)(tn * 128 + r) * KDIM + qo;
    }
    const uint32_t smb  = smem_u32(sm);
    const uint32_t dst0 = smb + rq * ROWB + qo * 4;

    float acc[4][8][4];
    #pragma unroll
    for (int i = 0; i < 4; i++)
        #pragma unroll
        for (int j = 0; j < 8; j++)
            #pragma unroll
            for (int k = 0; k < 4; k++) acc[i][j][k] = 0.f;

    auto issue = [&](int ch, int st) {
        const int koff = ch * 32;
        const uint32_t d = dst0 + st * STAGEB;
        #pragma unroll
        for (int k = 0; k < 4; k++) {
            const uint32_t dr = d + k * 32 * ROWB;
            CP16(dr,             gA[k] + koff);
            CP16(dr + 64,        gA[k] + koff + 16);
            CP16(dr + MATB,      gB[k] + koff);
            CP16(dr + MATB + 64, gB[k] + koff + 16);
        }
        CP_COMMIT();
    };

    issue(0, 0);
    issue(1, 1);

    const int warpRow = wm * 64;
    const int warpCol = wn * 64;

    for (int ch = 0; ch < 16; ch++) {
        if (ch < 15) CP_WAIT(1); else CP_WAIT(0);
        __syncthreads();                       // data ch visible + stage (ch-1)%3 free
        if (ch + 2 < 16) issue(ch + 2, (ch + 2) % 3);

        const int st = ch % NSTAGE;
        const char* sA = sm + st * STAGEB;
        const char* sB = sA + MATB;

        #pragma unroll
        for (int ks = 0; ks < 4; ks++) {
            const int kb = ks * 32 + lc * 4;           // byte offset in row
            uint32_t af[4][4], bf[8][2];
            #pragma unroll
            for (int mt = 0; mt < 4; mt++) {
                int r = warpRow + mt * 16 + lr4;
                const char* p0 = sA + r * ROWB + kb;
                const char* p1 = sA + (r + 8) * ROWB + kb;
                af[mt][0] = *(const uint32_t*)p0;
                af[mt][1] = *(const uint32_t*)p1;
                af[mt][2] = *(const uint32_t*)(p0 + 16);
                af[mt][3] = *(const uint32_t*)(p1 + 16);
            }
            #pragma unroll
            for (int nt = 0; nt < 8; nt++) {
                int cidx = warpCol + nt * 8 + lr4;
                const char* p = sB + cidx * ROWB + kb;
                bf[nt][0] = *(const uint32_t*)p;
                bf[nt][1] = *(const uint32_t*)(p + 16);
            }
            #pragma unroll
            for (int mt = 0; mt < 4; mt++)
                #pragma unroll
                for (int nt = 0; nt < 8; nt++)
                    mma_tf32(acc[mt][nt], af[mt], bf[nt]);
        }
        // no bottom barrier: next iteration's top barrier orders reuse
    }

    // epilogue: each thread owns float2 pairs at (r, c) and (r+8, c)
    #pragma unroll
    for (int mt = 0; mt < 4; mt++) {
        int r0 = tm * 128 + warpRow + mt * 16 + lr4;
        int r1 = r0 + 8;
        bool z0 = false, z1 = false;
        if (FINAL) { z0 = rowmask[r0] != 0; z1 = rowmask[r1] != 0; }
        #pragma unroll
        for (int nt = 0; nt < 8; nt++) {
            int c = tn * 128 + warpCol + nt * 8 + lc * 2;
            float2 v0 = make_float2(acc[mt][nt][0], acc[mt][nt][1]);
            float2 v1 = make_float2(acc[mt][nt][2], acc[mt][nt][3]);
            if (FINAL) {
                float2 bb = *(const float2*)(bias + c);
                if (z0) v0 = make_float2(0.f, 0.f);
                else    { v0.x += bb.x; v0.y += bb.y; }
                if (z1) v1 = make_float2(0.f, 0.f);
                else    { v1.x += bb.x; v1.y += bb.y; }
            }
            *(float2*)(C + (size_t)r0 * ldc + c) = v0;
            *(float2*)(C + (size_t)r1 * ldc + c) = v1;
        }
    }
}

// ---------------- fused attention (fp32; output tf32-rounded) ---------------
__global__ __launch_bounds__(256)
void attn_kernel(const float* __restrict__ q, const float* __restrict__ kv,
                 const int* __restrict__ pre_mask, float* __restrict__ out)
{
    __shared__ float smA[4096];
    __shared__ float smB[8192];
    const int tid = threadIdx.x;
    const int b = blockIdx.x >> 3;
    const int h = blockIdx.x & 7;

    const float* qbase = q  + (size_t)b * (NAG * EMB) + h * HDD;
    const float* kbase = kv + (size_t)b * (NE_ * 1024) + h * HDD;
    const float* vbase = kbase + EMB;

    {
        int i = tid;
        #pragma unroll
        for (int it = 0; it < 2; it++, i += 256) {
            int a = i >> 4, d4 = (i & 15) << 2;
            float4 v = *(const float4*)(qbase + (size_t)a * EMB + d4);
            smA[(d4+0)*32 + a] = v.x; smA[(d4+1)*32 + a] = v.y;
            smA[(d4+2)*32 + a] = v.z; smA[(d4+3)*32 + a] = v.w;
        }
    }
    {
        int i = tid;
        #pragma unroll
        for (int it = 0; it < 8; it++, i += 256) {
            int e = i >> 4, d4 = (i & 15) << 2;
            float4 v = *(const float4*)(kbase + (size_t)e * 1024 + d4);
            smB[(d4+0)*128 + e] = v.x; smB[(d4+1)*128 + e] = v.y;
            smB[(d4+2)*128 + e] = v.z; smB[(d4+3)*128 + e] = v.w;
        }
    }
    __syncthreads();

    const int e0 = (tid & 31) << 2;
    const int a0 = (tid >> 5) << 2;
    float lg[4][4];
    #pragma unroll
    for (int i = 0; i < 4; i++)
        #pragma unroll
        for (int j = 0; j < 4; j++) lg[i][j] = 0.f;

    #pragma unroll 8
    for (int d = 0; d < 64; d++) {
        float4 qa = *(const float4*)&smA[d*32  + a0];
        float4 kb = *(const float4*)&smB[d*128 + e0];
        float qv[4] = {qa.x, qa.y, qa.z, qa.w};
        float kk[4] = {kb.x, kb.y, kb.z, kb.w};
        #pragma unroll
        for (int i = 0; i < 4; i++)
            #pragma unroll
            for (int j = 0; j < 4; j++)
                lg[i][j] = fmaf(qv[i], kk[j], lg[i][j]);
    }
    __syncthreads();

    const int* mbase = pre_mask + (size_t)b * (NAG * NE_);
    #pragma unroll
    for (int i = 0; i < 4; i++) {
        int a = a0 + i;
        int4 m = *(const int4*)(mbase + a * NE_ + e0);
        float* lrow = &smA[a * 128 + e0];
        lrow[0] = m.x ? -1e30f : lg[i][0] * 0.125f;
        lrow[1] = m.y ? -1e30f : lg[i][1] * 0.125f;
        lrow[2] = m.z ? -1e30f : lg[i][2] * 0.125f;
        lrow[3] = m.w ? -1e30f : lg[i][3] * 0.125f;
    }
    {
        int i = tid;
        #pragma unroll
        for (int it = 0; it < 8; it++, i += 256) {
            int e = i >> 4, d4 = (i & 15) << 2;
            *(float4*)&smB[e*64 + d4] = *(const float4*)(vbase + (size_t)e * 1024 + d4);
        }
    }
    __syncthreads();

    {
        int a = tid >> 3, l = tid & 7;
        float* row = &smA[a * 128];
        float mx = -1e30f;
        #pragma unroll
        for (int j = 0; j < 16; j++) mx = fmaxf(mx, row[l + 8*j]);
        mx = fmaxf(mx, __shfl_xor_sync(0xffffffffu, mx, 1));
        mx = fmaxf(mx, __shfl_xor_sync(0xffffffffu, mx, 2));
        mx = fmaxf(mx, __shfl_xor_sync(0xffffffffu, mx, 4));
        float ex[16], sum = 0.f;
        #pragma unroll
        for (int j = 0; j < 16; j++) { float t = __expf(row[l + 8*j] - mx); ex[j] = t; sum += t; }
        sum += __shfl_xor_sync(0xffffffffu, sum, 1);
        sum += __shfl_xor_sync(0xffffffffu, sum, 2);
        sum += __shfl_xor_sync(0xffffffffu, sum, 4);
        float inv = (mx <= -1e29f) ? 0.f : (1.0f / sum);
        #pragma unroll
        for (int j = 0; j < 16; j++) row[l + 8*j] = ex[j] * inv;
    }
    __syncthreads();

    const int d0 = (tid & 31) << 1;
    const int a1 = (tid >> 5) << 2;
    float oa[4][2];
    #pragma unroll
    for (int i = 0; i < 4; i++) { oa[i][0] = 0.f; oa[i][1] = 0.f; }

    #pragma unroll 8
    for (int e = 0; e < 128; e++) {
        float2 vv = *(const float2*)&smB[e*64 + d0];
        #pragma unroll
        for (int i = 0; i < 4; i++) {
            float w = smA[(a1 + i) * 128 + e];
            oa[i][0] = fmaf(w, vv.x, oa[i][0]);
            oa[i][1] = fmaf(w, vv.y, oa[i][1]);
        }
    }
    float* obase = out + (size_t)b * (NAG * EMB) + h * HDD;
    #pragma unroll
    for (int i = 0; i < 4; i++)
        *(float2*)(obase + (size_t)(a1 + i) * EMB + d0) =
            make_float2(f2tf32f(oa[i][0]), f2tf32f(oa[i][1]));   // pre-round for out-GEMM
}

// ---------------- launch ---------------------------------------------------
extern "C" void kernel_launch(void* const* d_in, const int* in_sizes, int n_in,
                              void* d_out, int out_size)
{
    const float* entities  = (const float*)d_in[0];
    const int*   pre_mask  = (const int*)d_in[1];
    const int*   post_mask = (const int*)d_in[2];
    const float* W_in      = (const float*)d_in[3];
    const float* W_out     = (const float*)d_in[4];
    const float* b_out     = (const float*)d_in[5];
    float*       out       = (float*)d_out;

    float *kv_p, *q_p, *at_p, *er_p, *wr_p, *wor_p;
    cudaGetSymbolAddress((void**)&kv_p,  g_kv);
    cudaGetSymbolAddress((void**)&q_p,   g_q);
    cudaGetSymbolAddress((void**)&at_p,  g_at);
    cudaGetSymbolAddress((void**)&er_p,  g_er);
    cudaGetSymbolAddress((void**)&wr_p,  g_wr);
    cudaGetSymbolAddress((void**)&wor_p, g_wor);

    const int SMEM_BYTES = NSTAGE * STAGEB;   // 110592
    cudaFuncSetAttribute(gemm_tf32<false,false>, cudaFuncAttributeMaxDynamicSharedMemorySize, SMEM_BYTES);
    cudaFuncSetAttribute(gemm_tf32<true, false>, cudaFuncAttributeMaxDynamicSharedMemorySize, SMEM_BYTES);
    cudaFuncSetAttribute(gemm_tf32<false,true >, cudaFuncAttributeMaxDynamicSharedMemorySize, SMEM_BYTES);

    // tf32 rounding pre-pass (entities + weights)
    round_tf32<<<(BS_*NE_*KDIM/4 + 255)/256, 256>>>(entities, er_p, BS_*NE_*KDIM/4);
    round_tf32<<<(3*EMB*KDIM/4   + 255)/256, 256>>>(W_in,  wr_p,  3*EMB*KDIM/4);
    round_tf32<<<(EMB*EMB/4      + 255)/256, 256>>>(W_out, wor_p, EMB*EMB/4);

    // K|V projection: [131072,512] x W_in[512:1536]^T -> g_kv [131072,1024]
    gemm_tf32<false,false><<<dim3(8, 1024), 128, SMEM_BYTES>>>(
        er_p, wr_p + 512*512, kv_p, 1024, nullptr, nullptr);

    // Q projection (agent rows): [32768,512] x W_in[0:512]^T -> g_q
    gemm_tf32<true,false><<<dim3(4, 256), 128, SMEM_BYTES>>>(
        er_p, wr_p, q_p, 512, nullptr, nullptr);

    // attention (writes tf32-rounded output)
    attn_kernel<<<BS_ * NHD, 256>>>(q_p, kv_p, pre_mask, at_p);

    // out GEMM + bias + post-mask: [32768,512] x W_out^T
    gemm_tf32<false,true><<<dim3(4, 256), 128, SMEM_BYTES>>>(
        at_p, wor_p, out, 512, b_out, post_mask);
}

// round 8
// speedup vs baseline: 2.4461x; 1.0464x over previous
#include <cuda_runtime.h>
#include <cstdint>

#define BS_   1024
#define NE_   128
#define EMB   512
#define NAG   32
#define NHD   8
#define HDD   64
#define KDIM  512

// ---------------- scratch (device globals; allocation-guard safe) ----------
__device__ float g_kv[(size_t)BS_ * NE_ * 1024];   // [b*128+e][K(512)|V(512)]
__device__ float g_q [(size_t)BS_ * NAG * EMB];
__device__ float g_at[(size_t)BS_ * NAG * EMB];    // attention out (tf32-rounded)
__device__ float g_er[(size_t)BS_ * NE_ * KDIM];   // entities, tf32-rounded
__device__ float g_wr[3 * EMB * KDIM];             // W_in, tf32-rounded
__device__ float g_wor[EMB * EMB];                 // W_out, tf32-rounded

// ---------------- helpers ----------------------------------------------------
#define CP16(dst, src) \
    asm volatile("cp.async.cg.shared.global [%0], [%1], 16;" :: "r"(dst), "l"(src) : "memory")
#define CP_COMMIT()  asm volatile("cp.async.commit_group;" ::: "memory")
#define CP_WAIT(n)   asm volatile("cp.async.wait_group %0;" :: "n"(n) : "memory")

__device__ __forceinline__ uint32_t smem_u32(const void* p) {
    uint32_t a;
    asm("{ .reg .u64 t; cvta.to.shared.u64 t, %1; cvt.u32.u64 %0, t; }" : "=r"(a) : "l"(p));
    return a;
}
__device__ __forceinline__ float f2tf32f(float f) {
    uint32_t r;
    asm("cvt.rna.tf32.f32 %0, %1;" : "=r"(r) : "f"(f));
    return __uint_as_float(r);
}
__device__ __forceinline__ void mma_tf32(float* c, const uint32_t* a, const uint32_t* b) {
    asm volatile(
        "mma.sync.aligned.m16n8k8.row.col.f32.tf32.tf32.f32 "
        "{%0,%1,%2,%3}, {%4,%5,%6,%7}, {%8,%9}, {%0,%1,%2,%3};"
        : "+f"(c[0]), "+f"(c[1]), "+f"(c[2]), "+f"(c[3])
        : "r"(a[0]), "r"(a[1]), "r"(a[2]), "r"(a[3]), "r"(b[0]), "r"(b[1]));
}

// ---------------- tf32 rounding pre-pass ------------------------------------
__global__ __launch_bounds__(256)
void round_tf32(const float* __restrict__ x, float* __restrict__ y, int n4)
{
    int i = blockIdx.x * 256 + threadIdx.x;
    if (i >= n4) return;
    float4 v = ((const float4*)x)[i];
    v.x = f2tf32f(v.x); v.y = f2tf32f(v.y);
    v.z = f2tf32f(v.z); v.w = f2tf32f(v.w);
    ((float4*)y)[i] = v;
}

// ---------------- TF32 mma.sync GEMM (warp 64x64, frag pipeline) ------------
// C[M,N] = A[M,512] * B[N,512]^T; inputs pre-rounded to tf32 bit patterns.
// CTA 128x128, 128 thr (4 warps 2x2, each 64x64). BK=32, 3-stage cp.async ring,
// one barrier per chunk, 2-deep register pipeline for smem fragments.
// REMAP: A row r -> (r/32)*128 + r%32.  FINAL: +bias, zero rows with rowmask!=0.
#define FPITCH 36
#define ROWB   (FPITCH * 4)            // 144 bytes
#define MATB   (128 * ROWB)            // 18432 bytes per matrix
#define STAGEB (2 * MATB)              // A|B per stage
#define NSTAGE 3

template<bool REMAP, bool FINAL>
__global__ __launch_bounds__(128, 2)
void gemm_tf32(const float* __restrict__ A, const float* __restrict__ B,
               float* __restrict__ C, int ldc,
               const float* __restrict__ bias, const int* __restrict__ rowmask)
{
    extern __shared__ char sm[];
    const int tid  = threadIdx.x;
    const int wid  = tid >> 5, lane = tid & 31;
    const int wm   = wid >> 1, wn = wid & 1;          // warp grid 2x2
    const int tm   = blockIdx.y, tn = blockIdx.x;
    const int lr4  = lane >> 2;                        // 0..7
    const int lc   = lane & 3;                         // 0..3

    // global-load mapping: 4 threads per row (16B each), rows rq+32k
    const int rq = tid >> 2;             // 0..31
    const int qo = (tid & 3) << 2;       // float offset 0,4,8,12

    const float* gA[4];
    const float* gB[4];
    #pragma unroll
    for (int k = 0; k < 4; k++) {
        int r = rq + 32 * k;
        int arow = tm * 128 + r;
        if (REMAP) arow = ((arow >> 5) << 7) | (arow & 31);
        gA[k] = A + (size_t)arow * KDIM + qo;
        gB[k] = B + (size_t)(tn * 128 + r) * KDIM + qo;
    }
    const uint32_t smb  = smem_u32(sm);
    const uint32_t dst0 = smb + rq * ROWB + qo * 4;

    float acc[4][8][4];
    #pragma unroll
    for (int i = 0; i < 4; i++)
        #pragma unroll
        for (int j = 0; j < 8; j++)
            #pragma unroll
            for (int k = 0; k < 4; k++) acc[i][j][k] = 0.f;

    auto issue = [&](int ch, int st) {
        const int koff = ch * 32;
        const uint32_t d = dst0 + st * STAGEB;
        #pragma unroll
        for (int k = 0; k < 4; k++) {
            const uint32_t dr = d + k * 32 * ROWB;
            CP16(dr,             gA[k] + koff);
            CP16(dr + 64,        gA[k] + koff + 16);
            CP16(dr + MATB,      gB[k] + koff);
            CP16(dr + MATB + 64, gB[k] + koff + 16);
        }
        CP_COMMIT();
    };

    issue(0, 0);
    issue(1, 1);

    const int warpRow = wm * 64;
    const int warpCol = wn * 64;

    uint32_t af[2][4][4], bf[2][8][2];   // 2-deep fragment pipeline

    #define LOAD_FRAGS(buf, ks, sA, sB) do {                                   \
        const int kb_ = (ks) * 32 + lc * 4;                                    \
        _Pragma("unroll")                                                      \
        for (int mt = 0; mt < 4; mt++) {                                       \
            int r_ = warpRow + mt * 16 + lr4;                                  \
            const char* p0_ = (sA) + r_ * ROWB + kb_;                          \
            const char* p1_ = (sA) + (r_ + 8) * ROWB + kb_;                    \
            af[buf][mt][0] = *(const uint32_t*)p0_;                            \
            af[buf][mt][1] = *(const uint32_t*)p1_;                            \
            af[buf][mt][2] = *(const uint32_t*)(p0_ + 16);                     \
            af[buf][mt][3] = *(const uint32_t*)(p1_ + 16);                     \
        }                                                                      \
        _Pragma("unroll")                                                      \
        for (int nt = 0; nt < 8; nt++) {                                       \
            int c_ = warpCol + nt * 8 + lr4;                                   \
            const char* p_ = (sB) + c_ * ROWB + kb_;                           \
            bf[buf][nt][0] = *(const uint32_t*)p_;                             \
            bf[buf][nt][1] = *(const uint32_t*)(p_ + 16);                      \
        }                                                                      \
    } while (0)

    for (int ch = 0; ch < 16; ch++) {
        if (ch < 15) CP_WAIT(1); else CP_WAIT(0);
        __syncthreads();                       // data ch visible + stage (ch-1)%3 free

        const int st = ch % NSTAGE;
        const char* sA = sm + st * STAGEB;
        const char* sB = sA + MATB;

        LOAD_FRAGS(0, 0, sA, sB);              // first k-step fragments
        if (ch + 2 < 16) issue(ch + 2, (ch + 2) % 3);   // LDGSTS fills LDS shadow

        #pragma unroll
        for (int ks = 0; ks < 4; ks++) {
            const int cur = ks & 1;
            if (ks < 3) LOAD_FRAGS(cur ^ 1, ks + 1, sA, sB);
            #pragma unroll
            for (int mt = 0; mt < 4; mt++)
                #pragma unroll
                for (int nt = 0; nt < 8; nt++)
                    mma_tf32(acc[mt][nt], af[cur][mt], bf[cur][nt]);
        }
        // no bottom barrier: next iteration's top barrier orders stage reuse
    }
    #undef LOAD_FRAGS

    // epilogue: each thread owns float2 pairs at (r, c) and (r+8, c)
    #pragma unroll
    for (int mt = 0; mt < 4; mt++) {
        int r0 = tm * 128 + warpRow + mt * 16 + lr4;
        int r1 = r0 + 8;
        bool z0 = false, z1 = false;
        if (FINAL) { z0 = rowmask[r0] != 0; z1 = rowmask[r1] != 0; }
        #pragma unroll
        for (int nt = 0; nt < 8; nt++) {
            int c = tn * 128 + warpCol + nt * 8 + lc * 2;
            float2 v0 = make_float2(acc[mt][nt][0], acc[mt][nt][1]);
            float2 v1 = make_float2(acc[mt][nt][2], acc[mt][nt][3]);
            if (FINAL) {
                float2 bb = *(const float2*)(bias + c);
                if (z0) v0 = make_float2(0.f, 0.f);
                else    { v0.x += bb.x; v0.y += bb.y; }
                if (z1) v1 = make_float2(0.f, 0.f);
                else    { v1.x += bb.x; v1.y += bb.y; }
            }
            *(float2*)(C + (size_t)r0 * ldc + c) = v0;
            *(float2*)(C + (size_t)r1 * ldc + c) = v1;
        }
    }
}

// ---------------- fused attention (fp32; output tf32-rounded) ---------------
__global__ __launch_bounds__(256)
void attn_kernel(const float* __restrict__ q, const float* __restrict__ kv,
                 const int* __restrict__ pre_mask, float* __restrict__ out)
{
    __shared__ float smA[4096];
    __shared__ float smB[8192];
    const int tid = threadIdx.x;
    const int b = blockIdx.x >> 3;
    const int h = blockIdx.x & 7;

    const float* qbase = q  + (size_t)b * (NAG * EMB) + h * HDD;
    const float* kbase = kv + (size_t)b * (NE_ * 1024) + h * HDD;
    const float* vbase = kbase + EMB;

    {
        int i = tid;
        #pragma unroll
        for (int it = 0; it < 2; it++, i += 256) {
            int a = i >> 4, d4 = (i & 15) << 2;
            float4 v = *(const float4*)(qbase + (size_t)a * EMB + d4);
            smA[(d4+0)*32 + a] = v.x; smA[(d4+1)*32 + a] = v.y;
            smA[(d4+2)*32 + a] = v.z; smA[(d4+3)*32 + a] = v.w;
        }
    }
    {
        int i = tid;
        #pragma unroll
        for (int it = 0; it < 8; it++, i += 256) {
            int e = i >> 4, d4 = (i & 15) << 2;
            float4 v = *(const float4*)(kbase + (size_t)e * 1024 + d4);
            smB[(d4+0)*128 + e] = v.x; smB[(d4+1)*128 + e] = v.y;
            smB[(d4+2)*128 + e] = v.z; smB[(d4+3)*128 + e] = v.w;
        }
    }
    __syncthreads();

    const int e0 = (tid & 31) << 2;
    const int a0 = (tid >> 5) << 2;
    float lg[4][4];
    #pragma unroll
    for (int i = 0; i < 4; i++)
        #pragma unroll
        for (int j = 0; j < 4; j++) lg[i][j] = 0.f;

    #pragma unroll 8
    for (int d = 0; d < 64; d++) {
        float4 qa = *(const float4*)&smA[d*32  + a0];
        float4 kb = *(const float4*)&smB[d*128 + e0];
        float qv[4] = {qa.x, qa.y, qa.z, qa.w};
        float kk[4] = {kb.x, kb.y, kb.z, kb.w};
        #pragma unroll
        for (int i = 0; i < 4; i++)
            #pragma unroll
            for (int j = 0; j < 4; j++)
                lg[i][j] = fmaf(qv[i], kk[j], lg[i][j]);
    }
    __syncthreads();

    const int* mbase = pre_mask + (size_t)b * (NAG * NE_);
    #pragma unroll
    for (int i = 0; i < 4; i++) {
        int a = a0 + i;
        int4 m = *(const int4*)(mbase + a * NE_ + e0);
        float* lrow = &smA[a * 128 + e0];
        lrow[0] = m.x ? -1e30f : lg[i][0] * 0.125f;
        lrow[1] = m.y ? -1e30f : lg[i][1] * 0.125f;
        lrow[2] = m.z ? -1e30f : lg[i][2] * 0.125f;
        lrow[3] = m.w ? -1e30f : lg[i][3] * 0.125f;
    }
    {
        int i = tid;
        #pragma unroll
        for (int it = 0; it < 8; it++, i += 256) {
            int e = i >> 4, d4 = (i & 15) << 2;
            *(float4*)&smB[e*64 + d4] = *(const float4*)(vbase + (size_t)e * 1024 + d4);
        }
    }
    __syncthreads();

    {
        int a = tid >> 3, l = tid & 7;
        float* row = &smA[a * 128];
        float mx = -1e30f;
        #pragma unroll
        for (int j = 0; j < 16; j++) mx = fmaxf(mx, row[l + 8*j]);
        mx = fmaxf(mx, __shfl_xor_sync(0xffffffffu, mx, 1));
        mx = fmaxf(mx, __shfl_xor_sync(0xffffffffu, mx, 2));
        mx = fmaxf(mx, __shfl_xor_sync(0xffffffffu, mx, 4));
        float ex[16], sum = 0.f;
        #pragma unroll
        for (int j = 0; j < 16; j++) { float t = __expf(row[l + 8*j] - mx); ex[j] = t; sum += t; }
        sum += __shfl_xor_sync(0xffffffffu, sum, 1);
        sum += __shfl_xor_sync(0xffffffffu, sum, 2);
        sum += __shfl_xor_sync(0xffffffffu, sum, 4);
        float inv = (mx <= -1e29f) ? 0.f : (1.0f / sum);
        #pragma unroll
        for (int j = 0; j < 16; j++) row[l + 8*j] = ex[j] * inv;
    }
    __syncthreads();

    const int d0 = (tid & 31) << 1;
    const int a1 = (tid >> 5) << 2;
    float oa[4][2];
    #pragma unroll
    for (int i = 0; i < 4; i++) { oa[i][0] = 0.f; oa[i][1] = 0.f; }

    #pragma unroll 8
    for (int e = 0; e < 128; e++) {
        float2 vv = *(const float2*)&smB[e*64 + d0];
        #pragma unroll
        for (int i = 0; i < 4; i++) {
            float w = smA[(a1 + i) * 128 + e];
            oa[i][0] = fmaf(w, vv.x, oa[i][0]);
            oa[i][1] = fmaf(w, vv.y, oa[i][1]);
        }
    }
    float* obase = out + (size_t)b * (NAG * EMB) + h * HDD;
    #pragma unroll
    for (int i = 0; i < 4; i++)
        *(float2*)(obase + (size_t)(a1 + i) * EMB + d0) =
            make_float2(f2tf32f(oa[i][0]), f2tf32f(oa[i][1]));   // pre-round for out-GEMM
}

// ---------------- launch ---------------------------------------------------
extern "C" void kernel_launch(void* const* d_in, const int* in_sizes, int n_in,
                              void* d_out, int out_size)
{
    const float* entities  = (const float*)d_in[0];
    const int*   pre_mask  = (const int*)d_in[1];
    const int*   post_mask = (const int*)d_in[2];
    const float* W_in      = (const float*)d_in[3];
    const float* W_out     = (const float*)d_in[4];
    const float* b_out     = (const float*)d_in[5];
    float*       out       = (float*)d_out;

    float *kv_p, *q_p, *at_p, *er_p, *wr_p, *wor_p;
    cudaGetSymbolAddress((void**)&kv_p,  g_kv);
    cudaGetSymbolAddress((void**)&q_p,   g_q);
    cudaGetSymbolAddress((void**)&at_p,  g_at);
    cudaGetSymbolAddress((void**)&er_p,  g_er);
    cudaGetSymbolAddress((void**)&wr_p,  g_wr);
    cudaGetSymbolAddress((void**)&wor_p, g_wor);

    const int SMEM_BYTES = NSTAGE * STAGEB;   // 110592
    cudaFuncSetAttribute(gemm_tf32<false,false>, cudaFuncAttributeMaxDynamicSharedMemorySize, SMEM_BYTES);
    cudaFuncSetAttribute(gemm_tf32<true, false>, cudaFuncAttributeMaxDynamicSharedMemorySize, SMEM_BYTES);
    cudaFuncSetAttribute(gemm_tf32<false,true >, cudaFuncAttributeMaxDynamicSharedMemorySize, SMEM_BYTES);

    // tf32 rounding pre-pass (entities + weights)
    round_tf32<<<(BS_*NE_*KDIM/4 + 255)/256, 256>>>(entities, er_p, BS_*NE_*KDIM/4);
    round_tf32<<<(3*EMB*KDIM/4   + 255)/256, 256>>>(W_in,  wr_p,  3*EMB*KDIM/4);
    round_tf32<<<(EMB*EMB/4      + 255)/256, 256>>>(W_out, wor_p, EMB*EMB/4);

    // K|V projection: [131072,512] x W_in[512:1536]^T -> g_kv [131072,1024]
    gemm_tf32<false,false><<<dim3(8, 1024), 128, SMEM_BYTES>>>(
        er_p, wr_p + 512*512, kv_p, 1024, nullptr, nullptr);

    // Q projection (agent rows): [32768,512] x W_in[0:512]^T -> g_q
    gemm_tf32<true,false><<<dim3(4, 256), 128, SMEM_BYTES>>>(
        er_p, wr_p, q_p, 512, nullptr, nullptr);

    // attention (writes tf32-rounded output)
    attn_kernel<<<BS_ * NHD, 256>>>(q_p, kv_p, pre_mask, at_p);

    // out GEMM + bias + post-mask: [32768,512] x W_out^T
    gemm_tf32<false,true><<<dim3(4, 256), 128, SMEM_BYTES>>>(
        at_p, wor_p, out, 512, b_out, post_mask);
}

// round 9
// speedup vs baseline: 2.4912x; 1.0184x over previous
#include <cuda_runtime.h>
#include <cstdint>

#define BS_   1024
#define NE_   128
#define EMB   512
#define NAG   32
#define NHD   8
#define HDD   64
#define KDIM  512

// ---------------- scratch (device globals; allocation-guard safe) ----------
__device__ float g_kv[(size_t)BS_ * NE_ * 1024];   // [b*128+e][K(512)|V(512)]
__device__ float g_q [(size_t)BS_ * NAG * EMB];
__device__ float g_at[(size_t)BS_ * NAG * EMB];    // attention out (tf32-rounded)
__device__ float g_wr[3 * EMB * KDIM];             // W_in, tf32-rounded
__device__ float g_wor[EMB * EMB];                 // W_out, tf32-rounded

// ---------------- helpers ----------------------------------------------------
#define CP16(dst, src) \
    asm volatile("cp.async.cg.shared.global [%0], [%1], 16;" :: "r"(dst), "l"(src) : "memory")
#define CP_COMMIT()  asm volatile("cp.async.commit_group;" ::: "memory")
#define CP_WAIT(n)   asm volatile("cp.async.wait_group %0;" :: "n"(n) : "memory")

__device__ __forceinline__ uint32_t smem_u32(const void* p) {
    uint32_t a;
    asm("{ .reg .u64 t; cvta.to.shared.u64 t, %1; cvt.u32.u64 %0, t; }" : "=r"(a) : "l"(p));
    return a;
}
__device__ __forceinline__ float f2tf32f(float f) {
    uint32_t r;
    asm("cvt.rna.tf32.f32 %0, %1;" : "=r"(r) : "f"(f));
    return __uint_as_float(r);
}
__device__ __forceinline__ uint32_t cvt_tf32_u32(uint32_t raw) {
    uint32_t r;
    asm("cvt.rna.tf32.f32 %0, %1;" : "=r"(r) : "f"(__uint_as_float(raw)));
    return r;
}
__device__ __forceinline__ void mma_tf32(float* c, const uint32_t* a, const uint32_t* b) {
    asm volatile(
        "mma.sync.aligned.m16n8k8.row.col.f32.tf32.tf32.f32 "
        "{%0,%1,%2,%3}, {%4,%5,%6,%7}, {%8,%9}, {%0,%1,%2,%3};"
        : "+f"(c[0]), "+f"(c[1]), "+f"(c[2]), "+f"(c[3])
        : "r"(a[0]), "r"(a[1]), "r"(a[2]), "r"(a[3]), "r"(b[0]), "r"(b[1]));
}

// ---------------- tf32 rounding pre-pass (weights only) ---------------------
__global__ __launch_bounds__(256)
void round_tf32(const float* __restrict__ x, float* __restrict__ y, int n4)
{
    int i = blockIdx.x * 256 + threadIdx.x;
    if (i >= n4) return;
    float4 v = ((const float4*)x)[i];
    v.x = f2tf32f(v.x); v.y = f2tf32f(v.y);
    v.z = f2tf32f(v.z); v.w = f2tf32f(v.w);
    ((float4*)y)[i] = v;
}

// ---------------- TF32 GEMM body (warp 64x64, frag pipeline) ----------------
// C[128,128 tile] = A[*,512] * B[*,512]^T. A fragments tf32-rounded in-kernel
// (raw fp32 OK); B must be pre-rounded. CTA 128 thr (4 warps 2x2, each 64x64).
// BK=32, 3-stage cp.async ring, one barrier per chunk, 2-deep frag pipeline.
#define FPITCH 36
#define ROWB   (FPITCH * 4)            // 144 bytes
#define MATB   (128 * ROWB)            // 18432 bytes per matrix
#define STAGEB (2 * MATB)              // A|B per stage
#define NSTAGE 3

__device__ __forceinline__ void gemm_body(
    const float* __restrict__ A, const float* __restrict__ B,
    float* __restrict__ C, int ldc, int tm, int tn, bool remap,
    bool final_, const float* __restrict__ bias, const int* __restrict__ rowmask,
    char* sm)
{
    const int tid  = threadIdx.x;
    const int wid  = tid >> 5, lane = tid & 31;
    const int wm   = wid >> 1, wn = wid & 1;          // warp grid 2x2
    const int lr4  = lane >> 2;                        // 0..7
    const int lc   = lane & 3;                         // 0..3

    const int rq = tid >> 2;             // 0..31
    const int qo = (tid & 3) << 2;       // float offset 0,4,8,12

    const float* gA[4];
    const float* gB[4];
    #pragma unroll
    for (int k = 0; k < 4; k++) {
        int r = rq + 32 * k;
        int arow = tm * 128 + r;
        if (remap) arow = ((arow >> 5) << 7) | (arow & 31);
        gA[k] = A + (size_t)arow * KDIM + qo;
        gB[k] = B + (size_t)(tn * 128 + r) * KDIM + qo;
    }
    const uint32_t smb  = smem_u32(sm);
    const uint32_t dst0 = smb + rq * ROWB + qo * 4;

    float acc[4][8][4];
    #pragma unroll
    for (int i = 0; i < 4; i++)
        #pragma unroll
        for (int j = 0; j < 8; j++)
            #pragma unroll
            for (int k = 0; k < 4; k++) acc[i][j][k] = 0.f;

    auto issue = [&](int ch, int st) {
        const int koff = ch * 32;
        const uint32_t d = dst0 + st * STAGEB;
        #pragma unroll
        for (int k = 0; k < 4; k++) {
            const uint32_t dr = d + k * 32 * ROWB;
            CP16(dr,             gA[k] + koff);
            CP16(dr + 64,        gA[k] + koff + 16);
            CP16(dr + MATB,      gB[k] + koff);
            CP16(dr + MATB + 64, gB[k] + koff + 16);
        }
        CP_COMMIT();
    };

    issue(0, 0);
    issue(1, 1);

    const int warpRow = wm * 64;
    const int warpCol = wn * 64;

    uint32_t af[2][4][4], bf[2][8][2];   // 2-deep fragment pipeline

    #define LOAD_FRAGS(buf, ks, sA, sB) do {                                   \
        const int kb_ = (ks) * 32 + lc * 4;                                    \
        _Pragma("unroll")                                                      \
        for (int mt = 0; mt < 4; mt++) {                                       \
            int r_ = warpRow + mt * 16 + lr4;                                  \
            const char* p0_ = (sA) + r_ * ROWB + kb_;                          \
            const char* p1_ = (sA) + (r_ + 8) * ROWB + kb_;                    \
            af[buf][mt][0] = cvt_tf32_u32(*(const uint32_t*)p0_);              \
            af[buf][mt][1] = cvt_tf32_u32(*(const uint32_t*)p1_);              \
            af[buf][mt][2] = cvt_tf32_u32(*(const uint32_t*)(p0_ + 16));       \
            af[buf][mt][3] = cvt_tf32_u32(*(const uint32_t*)(p1_ + 16));       \
        }                                                                      \
        _Pragma("unroll")                                                      \
        for (int nt = 0; nt < 8; nt++) {                                       \
            int c_ = warpCol + nt * 8 + lr4;                                   \
            const char* p_ = (sB) + c_ * ROWB + kb_;                           \
            bf[buf][nt][0] = *(const uint32_t*)p_;                             \
            bf[buf][nt][1] = *(const uint32_t*)(p_ + 16);                      \
        }                                                                      \
    } while (0)

    for (int ch = 0; ch < 16; ch++) {
        if (ch < 15) CP_WAIT(1); else CP_WAIT(0);
        __syncthreads();                       // data ch visible + stage (ch-1)%3 free

        const int st = ch % NSTAGE;
        const char* sA = sm + st * STAGEB;
        const char* sB = sA + MATB;

        LOAD_FRAGS(0, 0, sA, sB);              // first k-step fragments
        if (ch + 2 < 16) issue(ch + 2, (ch + 2) % 3);   // LDGSTS fills LDS shadow

        #pragma unroll
        for (int ks = 0; ks < 4; ks++) {
            const int cur = ks & 1;
            if (ks < 3) LOAD_FRAGS(cur ^ 1, ks + 1, sA, sB);
            #pragma unroll
            for (int mt = 0; mt < 4; mt++)
                #pragma unroll
                for (int nt = 0; nt < 8; nt++)
                    mma_tf32(acc[mt][nt], af[cur][mt], bf[cur][nt]);
        }
    }
    #undef LOAD_FRAGS

    // epilogue
    #pragma unroll
    for (int mt = 0; mt < 4; mt++) {
        int r0 = tm * 128 + warpRow + mt * 16 + lr4;
        int r1 = r0 + 8;
        bool z0 = false, z1 = false;
        if (final_) { z0 = rowmask[r0] != 0; z1 = rowmask[r1] != 0; }
        #pragma unroll
        for (int nt = 0; nt < 8; nt++) {
            int c = tn * 128 + warpCol + nt * 8 + lc * 2;
            float2 v0 = make_float2(acc[mt][nt][0], acc[mt][nt][1]);
            float2 v1 = make_float2(acc[mt][nt][2], acc[mt][nt][3]);
            if (final_) {
                float2 bb = *(const float2*)(bias + c);
                if (z0) v0 = make_float2(0.f, 0.f);
                else    { v0.x += bb.x; v0.y += bb.y; }
                if (z1) v1 = make_float2(0.f, 0.f);
                else    { v1.x += bb.x; v1.y += bb.y; }
            }
            *(float2*)(C + (size_t)r0 * ldc + c) = v0;
            *(float2*)(C + (size_t)r1 * ldc + c) = v1;
        }
    }
}

// merged kv + q projection: y<1024 -> kv tile, y>=1024 -> q tile (agent rows)
__global__ __launch_bounds__(128, 2)
void gemm_kvq(const float* __restrict__ ent, const float* __restrict__ wr,
              float* __restrict__ kv, float* __restrict__ qo)
{
    extern __shared__ char sm[];
    const int bx = blockIdx.x, by = blockIdx.y;
    if (by < 1024) {
        gemm_body(ent, wr + 512 * 512, kv, 1024, by, bx, false, false, nullptr, nullptr, sm);
    } else {
        int id = (by - 1024) * 8 + bx;       // 0..1023 -> q grid (4 x 256)
        gemm_body(ent, wr, qo, 512, id >> 2, id & 3, true, false, nullptr, nullptr, sm);
    }
}

// out GEMM: + bias, zero rows with rowmask!=0
__global__ __launch_bounds__(128, 2)
void gemm_out(const float* __restrict__ A, const float* __restrict__ B,
              float* __restrict__ C,
              const float* __restrict__ bias, const int* __restrict__ rowmask)
{
    extern __shared__ char sm[];
    gemm_body(A, B, C, 512, blockIdx.y, blockIdx.x, false, true, bias, rowmask, sm);
}

// ---------------- fused attention (fp32; output tf32-rounded) ---------------
__global__ __launch_bounds__(256)
void attn_kernel(const float* __restrict__ q, const float* __restrict__ kv,
                 const int* __restrict__ pre_mask, float* __restrict__ out)
{
    __shared__ float smA[4096];
    __shared__ float smB[8192];
    const int tid = threadIdx.x;
    const int b = blockIdx.x >> 3;
    const int h = blockIdx.x & 7;

    const float* qbase = q  + (size_t)b * (NAG * EMB) + h * HDD;
    const float* kbase = kv + (size_t)b * (NE_ * 1024) + h * HDD;
    const float* vbase = kbase + EMB;

    {
        int i = tid;
        #pragma unroll
        for (int it = 0; it < 2; it++, i += 256) {
            int a = i >> 4, d4 = (i & 15) << 2;
            float4 v = *(const float4*)(qbase + (size_t)a * EMB + d4);
            smA[(d4+0)*32 + a] = v.x; smA[(d4+1)*32 + a] = v.y;
            smA[(d4+2)*32 + a] = v.z; smA[(d4+3)*32 + a] = v.w;
        }
    }
    {
        int i = tid;
        #pragma unroll
        for (int it = 0; it < 8; it++, i += 256) {
            int e = i >> 4, d4 = (i & 15) << 2;
            float4 v = *(const float4*)(kbase + (size_t)e * 1024 + d4);
            smB[(d4+0)*128 + e] = v.x; smB[(d4+1)*128 + e] = v.y;
            smB[(d4+2)*128 + e] = v.z; smB[(d4+3)*128 + e] = v.w;
        }
    }
    __syncthreads();

    const int e0 = (tid & 31) << 2;
    const int a0 = (tid >> 5) << 2;
    float lg[4][4];
    #pragma unroll
    for (int i = 0; i < 4; i++)
        #pragma unroll
        for (int j = 0; j < 4; j++) lg[i][j] = 0.f;

    #pragma unroll 8
    for (int d = 0; d < 64; d++) {
        float4 qa = *(const float4*)&smA[d*32  + a0];
        float4 kb = *(const float4*)&smB[d*128 + e0];
        float qv[4] = {qa.x, qa.y, qa.z, qa.w};
        float kk[4] = {kb.x, kb.y, kb.z, kb.w};
        #pragma unroll
        for (int i = 0; i < 4; i++)
            #pragma unroll
            for (int j = 0; j < 4; j++)
                lg[i][j] = fmaf(qv[i], kk[j], lg[i][j]);
    }
    __syncthreads();

    const int* mbase = pre_mask + (size_t)b * (NAG * NE_);
    #pragma unroll
    for (int i = 0; i < 4; i++) {
        int a = a0 + i;
        int4 m = *(const int4*)(mbase + a * NE_ + e0);
        float* lrow = &smA[a * 128 + e0];
        lrow[0] = m.x ? -1e30f : lg[i][0] * 0.125f;
        lrow[1] = m.y ? -1e30f : lg[i][1] * 0.125f;
        lrow[2] = m.z ? -1e30f : lg[i][2] * 0.125f;
        lrow[3] = m.w ? -1e30f : lg[i][3] * 0.125f;
    }
    {
        int i = tid;
        #pragma unroll
        for (int it = 0; it < 8; it++, i += 256) {
            int e = i >> 4, d4 = (i & 15) << 2;
            *(float4*)&smB[e*64 + d4] = *(const float4*)(vbase + (size_t)e * 1024 + d4);
        }
    }
    __syncthreads();

    {
        int a = tid >> 3, l = tid & 7;
        float* row = &smA[a * 128];
        float mx = -1e30f;
        #pragma unroll
        for (int j = 0; j < 16; j++) mx = fmaxf(mx, row[l + 8*j]);
        mx = fmaxf(mx, __shfl_xor_sync(0xffffffffu, mx, 1));
        mx = fmaxf(mx, __shfl_xor_sync(0xffffffffu, mx, 2));
        mx = fmaxf(mx, __shfl_xor_sync(0xffffffffu, mx, 4));
        float ex[16], sum = 0.f;
        #pragma unroll
        for (int j = 0; j < 16; j++) { float t = __expf(row[l + 8*j] - mx); ex[j] = t; sum += t; }
        sum += __shfl_xor_sync(0xffffffffu, sum, 1);
        sum += __shfl_xor_sync(0xffffffffu, sum, 2);
        sum += __shfl_xor_sync(0xffffffffu, sum, 4);
        float inv = (mx <= -1e29f) ? 0.f : (1.0f / sum);
        #pragma unroll
        for (int j = 0; j < 16; j++) row[l + 8*j] = ex[j] * inv;
    }
    __syncthreads();

    const int d0 = (tid & 31) << 1;
    const int a1 = (tid >> 5) << 2;
    float oa[4][2];
    #pragma unroll
    for (int i = 0; i < 4; i++) { oa[i][0] = 0.f; oa[i][1] = 0.f; }

    #pragma unroll 8
    for (int e = 0; e < 128; e++) {
        float2 vv = *(const float2*)&smB[e*64 + d0];
        #pragma unroll
        for (int i = 0; i < 4; i++) {
            float w = smA[(a1 + i) * 128 + e];
            oa[i][0] = fmaf(w, vv.x, oa[i][0]);
            oa[i][1] = fmaf(w, vv.y, oa[i][1]);
        }
    }
    float* obase = out + (size_t)b * (NAG * EMB) + h * HDD;
    #pragma unroll
    for (int i = 0; i < 4; i++)
        *(float2*)(obase + (size_t)(a1 + i) * EMB + d0) =
            make_float2(f2tf32f(oa[i][0]), f2tf32f(oa[i][1]));   // pre-round for out-GEMM
}

// ---------------- launch ---------------------------------------------------
extern "C" void kernel_launch(void* const* d_in, const int* in_sizes, int n_in,
                              void* d_out, int out_size)
{
    const float* entities  = (const float*)d_in[0];
    const int*   pre_mask  = (const int*)d_in[1];
    const int*   post_mask = (const int*)d_in[2];
    const float* W_in      = (const float*)d_in[3];
    const float* W_out     = (const float*)d_in[4];
    const float* b_out     = (const float*)d_in[5];
    float*       out       = (float*)d_out;

    float *kv_p, *q_p, *at_p, *wr_p, *wor_p;
    cudaGetSymbolAddress((void**)&kv_p,  g_kv);
    cudaGetSymbolAddress((void**)&q_p,   g_q);
    cudaGetSymbolAddress((void**)&at_p,  g_at);
    cudaGetSymbolAddress((void**)&wr_p,  g_wr);
    cudaGetSymbolAddress((void**)&wor_p, g_wor);

    const int SMEM_BYTES = NSTAGE * STAGEB;   // 110592
    cudaFuncSetAttribute(gemm_kvq, cudaFuncAttributeMaxDynamicSharedMemorySize, SMEM_BYTES);
    cudaFuncSetAttribute(gemm_out, cudaFuncAttributeMaxDynamicSharedMemorySize, SMEM_BYTES);

    // tf32 rounding pre-pass (weights only; entities rounded in-kernel)
    round_tf32<<<(3*EMB*KDIM/4 + 255)/256, 256>>>(W_in,  wr_p,  3*EMB*KDIM/4);
    round_tf32<<<(EMB*EMB/4    + 255)/256, 256>>>(W_out, wor_p, EMB*EMB/4);

    // merged K|V projection (y<1024) + Q projection (y>=1024)
    gemm_kvq<<<dim3(8, 1152), 128, SMEM_BYTES>>>(entities, wr_p, kv_p, q_p);

    // attention (writes tf32-rounded output)
    attn_kernel<<<BS_ * NHD, 256>>>(q_p, kv_p, pre_mask, at_p);

    // out GEMM + bias + post-mask: [32768,512] x W_out^T
    gemm_out<<<dim3(4, 256), 128, SMEM_BYTES>>>(at_p, wor_p, out, b_out, post_mask);
}

// round 10
// speedup vs baseline: 2.6085x; 1.0471x over previous
#include <cuda_runtime.h>
#include <cuda_bf16.h>
#include <cstdint>

#define BS_   1024
#define NE_   128
#define EMB   512
#define NAG   32
#define NHD   8
#define HDD   64
#define KDIM  512

// ---------------- scratch (device globals; allocation-guard safe) ----------
__device__ float g_kv[(size_t)BS_ * NE_ * 1024];   // [b*128+e][K(512)|V(512)]
__device__ float g_q [(size_t)BS_ * NAG * EMB];
__device__ float g_at[(size_t)BS_ * NAG * EMB];    // attention output

// ---------------- helpers ----------------------------------------------------
#define CP16(dst, src) \
    asm volatile("cp.async.cg.shared.global [%0], [%1], 16;" :: "r"(dst), "l"(src) : "memory")
#define CP_COMMIT()  asm volatile("cp.async.commit_group;" ::: "memory")
#define CP_WAIT(n)   asm volatile("cp.async.wait_group %0;" :: "n"(n) : "memory")

__device__ __forceinline__ uint32_t smem_u32(const void* p) {
    uint32_t a;
    asm("{ .reg .u64 t; cvta.to.shared.u64 t, %1; cvt.u32.u64 %0, t; }" : "=r"(a) : "l"(p));
    return a;
}
__device__ __forceinline__ uint32_t cvt_tf32_u32(uint32_t raw) {
    uint32_t r;
    asm("cvt.rna.tf32.f32 %0, %1;" : "=r"(r) : "f"(__uint_as_float(raw)));
    return r;
}
__device__ __forceinline__ void mma_tf32(float* c, const uint32_t* a, const uint32_t* b) {
    asm volatile(
        "mma.sync.aligned.m16n8k8.row.col.f32.tf32.tf32.f32 "
        "{%0,%1,%2,%3}, {%4,%5,%6,%7}, {%8,%9}, {%0,%1,%2,%3};"
        : "+f"(c[0]), "+f"(c[1]), "+f"(c[2]), "+f"(c[3])
        : "r"(a[0]), "r"(a[1]), "r"(a[2]), "r"(a[3]), "r"(b[0]), "r"(b[1]));
}
__device__ __forceinline__ void mma_bf16(float* c, const uint32_t* a, const uint32_t* b) {
    asm volatile(
        "mma.sync.aligned.m16n8k16.row.col.f32.bf16.bf16.f32 "
        "{%0,%1,%2,%3}, {%4,%5,%6,%7}, {%8,%9}, {%0,%1,%2,%3};"
        : "+f"(c[0]), "+f"(c[1]), "+f"(c[2]), "+f"(c[3])
        : "r"(a[0]), "r"(a[1]), "r"(a[2]), "r"(a[3]), "r"(b[0]), "r"(b[1]));
}
// split two fp32 into packed bf16x2 hi and lo words (low half = first arg)
__device__ __forceinline__ void split2(float x, float y, uint32_t& hi, uint32_t& lo) {
    __nv_bfloat16 hx = __float2bfloat16(x), hy = __float2bfloat16(y);
    __nv_bfloat16 lx = __float2bfloat16(x - __bfloat162float(hx));
    __nv_bfloat16 ly = __float2bfloat16(y - __bfloat162float(hy));
    __nv_bfloat162 hp(hx, hy), lp(lx, ly);
    hi = *(uint32_t*)&hp; lo = *(uint32_t*)&lp;
}

// ---------------- TF32 GEMM body (warp 64x64, frag pipeline) ----------------
// C = A[*,512] * B[*,512]^T, raw fp32 inputs; A and B fragments tf32-rounded
// in-register. CTA 128 thr (4 warps 2x2, each 64x64), BK=32, 3-stage ring.
#define FPITCH 36
#define ROWB   (FPITCH * 4)
#define MATB   (128 * ROWB)
#define STAGEB (2 * MATB)
#define NSTAGE 3

__device__ __forceinline__ void gemm_body(
    const float* __restrict__ A, const float* __restrict__ B,
    float* __restrict__ C, int ldc, int tm, int tn, bool remap,
    bool final_, const float* __restrict__ bias, const int* __restrict__ rowmask,
    char* sm)
{
    const int tid  = threadIdx.x;
    const int wid  = tid >> 5, lane = tid & 31;
    const int wm   = wid >> 1, wn = wid & 1;
    const int lr4  = lane >> 2;
    const int lc   = lane & 3;

    const int rq = tid >> 2;
    const int qo = (tid & 3) << 2;

    const float* gA[4];
    const float* gB[4];
    #pragma unroll
    for (int k = 0; k < 4; k++) {
        int r = rq + 32 * k;
        int arow = tm * 128 + r;
        if (remap) arow = ((arow >> 5) << 7) | (arow & 31);
        gA[k] = A + (size_t)arow * KDIM + qo;
        gB[k] = B + (size_t)(tn * 128 + r) * KDIM + qo;
    }
    const uint32_t smb  = smem_u32(sm);
    const uint32_t dst0 = smb + rq * ROWB + qo * 4;

    float acc[4][8][4];
    #pragma unroll
    for (int i = 0; i < 4; i++)
        #pragma unroll
        for (int j = 0; j < 8; j++)
            #pragma unroll
            for (int k = 0; k < 4; k++) acc[i][j][k] = 0.f;

    auto issue = [&](int ch, int st) {
        const int koff = ch * 32;
        const uint32_t d = dst0 + st * STAGEB;
        #pragma unroll
        for (int k = 0; k < 4; k++) {
            const uint32_t dr = d + k * 32 * ROWB;
            CP16(dr,             gA[k] + koff);
            CP16(dr + 64,        gA[k] + koff + 16);
            CP16(dr + MATB,      gB[k] + koff);
            CP16(dr + MATB + 64, gB[k] + koff + 16);
        }
        CP_COMMIT();
    };

    issue(0, 0);
    issue(1, 1);

    const int warpRow = wm * 64;
    const int warpCol = wn * 64;

    uint32_t af[2][4][4], bf[2][8][2];

    #define LOAD_FRAGS(buf, ks, sA, sB) do {                                   \
        const int kb_ = (ks) * 32 + lc * 4;                                    \
        _Pragma("unroll")                                                      \
        for (int mt = 0; mt < 4; mt++) {                                       \
            int r_ = warpRow + mt * 16 + lr4;                                  \
            const char* p0_ = (sA) + r_ * ROWB + kb_;                          \
            const char* p1_ = (sA) + (r_ + 8) * ROWB + kb_;                    \
            af[buf][mt][0] = cvt_tf32_u32(*(const uint32_t*)p0_);              \
            af[buf][mt][1] = cvt_tf32_u32(*(const uint32_t*)p1_);              \
            af[buf][mt][2] = cvt_tf32_u32(*(const uint32_t*)(p0_ + 16));       \
            af[buf][mt][3] = cvt_tf32_u32(*(const uint32_t*)(p1_ + 16));       \
        }                                                                      \
        _Pragma("unroll")                                                      \
        for (int nt = 0; nt < 8; nt++) {                                       \
            int c_ = warpCol + nt * 8 + lr4;                                   \
            const char* p_ = (sB) + c_ * ROWB + kb_;                           \
            bf[buf][nt][0] = cvt_tf32_u32(*(const uint32_t*)p_);               \
            bf[buf][nt][1] = cvt_tf32_u32(*(const uint32_t*)(p_ + 16));        \
        }                                                                      \
    } while (0)

    for (int ch = 0; ch < 16; ch++) {
        if (ch < 15) CP_WAIT(1); else CP_WAIT(0);
        __syncthreads();

        const int st = ch % NSTAGE;
        const char* sA = sm + st * STAGEB;
        const char* sB = sA + MATB;

        LOAD_FRAGS(0, 0, sA, sB);
        if (ch + 2 < 16) issue(ch + 2, (ch + 2) % 3);

        #pragma unroll
        for (int ks = 0; ks < 4; ks++) {
            const int cur = ks & 1;
            if (ks < 3) LOAD_FRAGS(cur ^ 1, ks + 1, sA, sB);
            #pragma unroll
            for (int mt = 0; mt < 4; mt++)
                #pragma unroll
                for (int nt = 0; nt < 8; nt++)
                    mma_tf32(acc[mt][nt], af[cur][mt], bf[cur][nt]);
        }
    }
    #undef LOAD_FRAGS

    #pragma unroll
    for (int mt = 0; mt < 4; mt++) {
        int r0 = tm * 128 + warpRow + mt * 16 + lr4;
        int r1 = r0 + 8;
        bool z0 = false, z1 = false;
        if (final_) { z0 = rowmask[r0] != 0; z1 = rowmask[r1] != 0; }
        #pragma unroll
        for (int nt = 0; nt < 8; nt++) {
            int c = tn * 128 + warpCol + nt * 8 + lc * 2;
            float2 v0 = make_float2(acc[mt][nt][0], acc[mt][nt][1]);
            float2 v1 = make_float2(acc[mt][nt][2], acc[mt][nt][3]);
            if (final_) {
                float2 bb = *(const float2*)(bias + c);
                if (z0) v0 = make_float2(0.f, 0.f);
                else    { v0.x += bb.x; v0.y += bb.y; }
                if (z1) v1 = make_float2(0.f, 0.f);
                else    { v1.x += bb.x; v1.y += bb.y; }
            }
            *(float2*)(C + (size_t)r0 * ldc + c) = v0;
            *(float2*)(C + (size_t)r1 * ldc + c) = v1;
        }
    }
}

__global__ __launch_bounds__(128, 2)
void gemm_kvq(const float* __restrict__ ent, const float* __restrict__ win,
              float* __restrict__ kv, float* __restrict__ qo)
{
    extern __shared__ char sm[];
    const int bx = blockIdx.x, by = blockIdx.y;
    if (by < 1024) {
        gemm_body(ent, win + 512 * 512, kv, 1024, by, bx, false, false, nullptr, nullptr, sm);
    } else {
        int id = (by - 1024) * 8 + bx;
        gemm_body(ent, win, qo, 512, id >> 2, id & 3, true, false, nullptr, nullptr, sm);
    }
}

__global__ __launch_bounds__(128, 2)
void gemm_out(const float* __restrict__ A, const float* __restrict__ B,
              float* __restrict__ C,
              const float* __restrict__ bias, const int* __restrict__ rowmask)
{
    extern __shared__ char sm[];
    gemm_body(A, B, C, 512, blockIdx.y, blockIdx.x, false, true, bias, rowmask, sm);
}

// ---------------- attention: bf16x3 tensor-core version ---------------------
// block = (b,h), 256 thr (8 warps). hi/lo bf16 smem tiles, 2 MMA phases.
// word-offset layout in dynamic smem:
#define OQH 0                    // qhi [32][36]
#define OQL 1152                 // qlo
#define OKH 2304                 // khi [128][36]
#define OKL 6912                 // klo
#define OVH 11520                // vt hi [64 d][68 e-pairs]
#define OVL 15872                // vt lo
#define OWH 20224                // w hi [32][68]
#define OWL 22400                // w lo
#define OU  24576                // union: v fp32 stage [128][21] / logits [32][132]
#define ATTN_WORDS 28800         // 115200 bytes

__global__ __launch_bounds__(256, 2)
void attn_kernel(const float* __restrict__ q, const float* __restrict__ kv,
                 const int* __restrict__ pre_mask, float* __restrict__ out)
{
    extern __shared__ uint32_t smw[];
    float* smf = (float*)smw;
    const int tid = threadIdx.x;
    const int wid = tid >> 5, lane = tid & 31;
    const int lr4 = lane >> 2, lc = lane & 3;
    const int wm  = wid >> 2, wn = wid & 3;          // warp grid 2x4
    const int b = blockIdx.x >> 3;
    const int h = blockIdx.x & 7;

    const float* qbase = q  + (size_t)b * (NAG * EMB) + h * HDD;
    const float* kbase = kv + (size_t)b * (NE_ * 1024) + h * HDD;
    const float* vbase = kbase + EMB;

    // P1: q -> qhi/qlo bf16 pairs (32 rows x 32 words)
    #pragma unroll
    for (int it = 0; it < 4; it++) {
        int i = tid + it * 256;
        int a = i >> 5, wd = i & 31;
        float2 x = *(const float2*)(qbase + (size_t)a * EMB + wd * 2);
        uint32_t hi, lo; split2(x.x, x.y, hi, lo);
        smw[OQH + a * 36 + wd] = hi;
        smw[OQL + a * 36 + wd] = lo;
    }
    // P2: k -> khi/klo (128 rows x 32 words)
    #pragma unroll
    for (int it = 0; it < 16; it++) {
        int i = tid + it * 256;
        int e = i >> 5, wd = i & 31;
        float2 x = *(const float2*)(kbase + (size_t)e * 1024 + wd * 2);
        uint32_t hi, lo; split2(x.x, x.y, hi, lo);
        smw[OKH + e * 36 + wd] = hi;
        smw[OKL + e * 36 + wd] = lo;
    }
    // P3: v -> transposed vt hi/lo, via fp32 staging in 4 d-quarters
    for (int dq = 0; dq < 4; dq++) {
        const int d0 = dq * 16;
        #pragma unroll
        for (int it = 0; it < 2; it++) {
            int i = tid + it * 256;
            int e = i >> 2, f = (i & 3) * 4;
            float4 x = *(const float4*)(vbase + (size_t)e * 1024 + d0 + f);
            float* s = smf + OU + e * 21 + f;
            s[0] = x.x; s[1] = x.y; s[2] = x.z; s[3] = x.w;
        }
        __syncthreads();
        #pragma unroll
        for (int it = 0; it < 4; it++) {
            int i = tid + it * 256;
            int dl = i >> 6, ep = i & 63;
            float a0 = smf[OU + (2 * ep)     * 21 + dl];
            float a1 = smf[OU + (2 * ep + 1) * 21 + dl];
            uint32_t hi, lo; split2(a0, a1, hi, lo);
            smw[OVH + (d0 + dl) * 68 + ep] = hi;
            smw[OVL + (d0 + dl) * 68 + ep] = lo;
        }
        __syncthreads();
    }

    // P4: logits = q @ k^T  (bf16x3), warp tile 16a x 32e, K=64
    float lg[4][4];
    #pragma unroll
    for (int i = 0; i < 4; i++)
        #pragma unroll
        for (int j = 0; j < 4; j++) lg[i][j] = 0.f;

    const int rowA = wm * 16 + lr4;
    #pragma unroll
    for (int ks = 0; ks < 4; ks++) {
        const int kw = lc + ks * 8;
        uint32_t ah[4], al[4];
        ah[0] = smw[OQH + rowA * 36 + kw];       al[0] = smw[OQL + rowA * 36 + kw];
        ah[1] = smw[OQH + (rowA + 8) * 36 + kw]; al[1] = smw[OQL + (rowA + 8) * 36 + kw];
        ah[2] = smw[OQH + rowA * 36 + kw + 4];   al[2] = smw[OQL + rowA * 36 + kw + 4];
        ah[3] = smw[OQH + (rowA + 8) * 36 + kw + 4]; al[3] = smw[OQL + (rowA + 8) * 36 + kw + 4];
        #pragma unroll
        for (int nt = 0; nt < 4; nt++) {
            int col = wn * 32 + nt * 8 + lr4;
            uint32_t bh[2], bl[2];
            bh[0] = smw[OKH + col * 36 + kw];     bh[1] = smw[OKH + col * 36 + kw + 4];
            bl[0] = smw[OKL + col * 36 + kw];     bl[1] = smw[OKL + col * 36 + kw + 4];
            mma_bf16(lg[nt], ah, bh);
            mma_bf16(lg[nt], ah, bl);
            mma_bf16(lg[nt], al, bh);
        }
    }

    // P5: masked, scaled logits -> fp32 smem (pitch 132)
    {
        const int* mb = pre_mask + (size_t)b * (NAG * NE_);
        int r0 = wm * 16 + lr4, r1 = r0 + 8;
        #pragma unroll
        for (int nt = 0; nt < 4; nt++) {
            int c = wn * 32 + nt * 8 + lc * 2;
            int2 m0 = *(const int2*)(mb + r0 * NE_ + c);
            int2 m1 = *(const int2*)(mb + r1 * NE_ + c);
            smf[OU + r0 * 132 + c]     = m0.x ? -1e30f : lg[nt][0] * 0.125f;
            smf[OU + r0 * 132 + c + 1] = m0.y ? -1e30f : lg[nt][1] * 0.125f;
            smf[OU + r1 * 132 + c]     = m1.x ? -1e30f : lg[nt][2] * 0.125f;
            smf[OU + r1 * 132 + c + 1] = m1.y ? -1e30f : lg[nt][3] * 0.125f;
        }
    }
    __syncthreads();

    // P6: softmax over e (8 threads per agent row)
    {
        int a = tid >> 3, l = tid & 7;
        float* row = smf + OU + a * 132;
        float mx = -1e30f;
        #pragma unroll
        for (int j = 0; j < 16; j++) mx = fmaxf(mx, row[l + 8 * j]);
        mx = fmaxf(mx, __shfl_xor_sync(0xffffffffu, mx, 1));
        mx = fmaxf(mx, __shfl_xor_sync(0xffffffffu, mx, 2));
        mx = fmaxf(mx, __shfl_xor_sync(0xffffffffu, mx, 4));
        float ex[16], sum = 0.f;
        #pragma unroll
        for (int j = 0; j < 16; j++) { float t = __expf(row[l + 8 * j] - mx); ex[j] = t; sum += t; }
        sum += __shfl_xor_sync(0xffffffffu, sum, 1);
        sum += __shfl_xor_sync(0xffffffffu, sum, 2);
        sum += __shfl_xor_sync(0xffffffffu, sum, 4);
        float inv = (mx <= -1e29f) ? 0.f : (1.0f / sum);
        #pragma unroll
        for (int j = 0; j < 16; j++) row[l + 8 * j] = ex[j] * inv;
    }
    __syncthreads();

    // P7: w -> whi/wlo bf16 pairs (32 rows x 64 words)
    #pragma unroll
    for (int it = 0; it < 8; it++) {
        int i = tid + it * 256;
        int a = i >> 6, ep = i & 63;
        float2 x = *(const float2*)(smf + OU + a * 132 + 2 * ep);
        uint32_t hi, lo; split2(x.x, x.y, hi, lo);
        smw[OWH + a * 68 + ep] = hi;
        smw[OWL + a * 68 + ep] = lo;
    }
    __syncthreads();

    // P8: attn = w @ v  (bf16x3), warp tile 16a x 16d, K=128
    float oa[2][4];
    #pragma unroll
    for (int i = 0; i < 2; i++)
        #pragma unroll
        for (int j = 0; j < 4; j++) oa[i][j] = 0.f;

    #pragma unroll
    for (int ks = 0; ks < 8; ks++) {
        const int kw = lc + ks * 8;
        uint32_t ah[4], al[4];
        ah[0] = smw[OWH + rowA * 68 + kw];           al[0] = smw[OWL + rowA * 68 + kw];
        ah[1] = smw[OWH + (rowA + 8) * 68 + kw];     al[1] = smw[OWL + (rowA + 8) * 68 + kw];
        ah[2] = smw[OWH + rowA * 68 + kw + 4];       al[2] = smw[OWL + rowA * 68 + kw + 4];
        ah[3] = smw[OWH + (rowA + 8) * 68 + kw + 4]; al[3] = smw[OWL + (rowA + 8) * 68 + kw + 4];
        #pragma unroll
        for (int nt = 0; nt < 2; nt++) {
            int col = wn * 16 + nt * 8 + lr4;        // d row of vt
            uint32_t bh[2], bl[2];
            bh[0] = smw[OVH + col * 68 + kw];  bh[1] = smw[OVH + col * 68 + kw + 4];
            bl[0] = smw[OVL + col * 68 + kw];  bl[1] = smw[OVL + col * 68 + kw + 4];
            mma_bf16(oa[nt], ah, bh);
            mma_bf16(oa[nt], ah, bl);
            mma_bf16(oa[nt], al, bh);
        }
    }

    // P9: write attn out
    float* ob = out + (size_t)b * (NAG * EMB) + h * HDD;
    #pragma unroll
    for (int nt = 0; nt < 2; nt++) {
        int d0 = wn * 16 + nt * 8 + lc * 2;
        *(float2*)(ob + (size_t)rowA * EMB + d0)       = make_float2(oa[nt][0], oa[nt][1]);
        *(float2*)(ob + (size_t)(rowA + 8) * EMB + d0) = make_float2(oa[nt][2], oa[nt][3]);
    }
}

// ---------------- launch ---------------------------------------------------
extern "C" void kernel_launch(void* const* d_in, const int* in_sizes, int n_in,
                              void* d_out, int out_size)
{
    const float* entities  = (const float*)d_in[0];
    const int*   pre_mask  = (const int*)d_in[1];
    const int*   post_mask = (const int*)d_in[2];
    const float* W_in      = (const float*)d_in[3];
    const float* W_out     = (const float*)d_in[4];
    const float* b_out     = (const float*)d_in[5];
    float*       out       = (float*)d_out;

    float *kv_p, *q_p, *at_p;
    cudaGetSymbolAddress((void**)&kv_p, g_kv);
    cudaGetSymbolAddress((void**)&q_p,  g_q);
    cudaGetSymbolAddress((void**)&at_p, g_at);

    const int SMEM_BYTES = NSTAGE * STAGEB;       // 110592
    const int ATTN_BYTES = ATTN_WORDS * 4;        // 115200
    cudaFuncSetAttribute(gemm_kvq,   cudaFuncAttributeMaxDynamicSharedMemorySize, SMEM_BYTES);
    cudaFuncSetAttribute(gemm_out,   cudaFuncAttributeMaxDynamicSharedMemorySize, SMEM_BYTES);
    cudaFuncSetAttribute(attn_kernel, cudaFuncAttributeMaxDynamicSharedMemorySize, ATTN_BYTES);

    // merged K|V projection (y<1024) + Q projection (y>=1024); raw weights (tf32 cvt in-kernel)
    gemm_kvq<<<dim3(8, 1152), 128, SMEM_BYTES>>>(entities, W_in, kv_p, q_p);

    // tensor-core attention (bf16x3)
    attn_kernel<<<BS_ * NHD, 256, ATTN_BYTES>>>(q_p, kv_p, pre_mask, at_p);

    // out GEMM + bias + post-mask
    gemm_out<<<dim3(4, 256), 128, SMEM_BYTES>>>(at_p, W_out, out, b_out, post_mask);
}

// round 11
// speedup vs baseline: 2.7157x; 1.0411x over previous
#include <cuda_runtime.h>
#include <cuda_bf16.h>
#include <cstdint>

#define BS_   1024
#define NE_   128
#define EMB   512
#define NAG   32
#define NHD   8
#define HDD   64
#define KDIM  512

// ---------------- scratch (device globals; allocation-guard safe) ----------
__device__ float g_kv[(size_t)BS_ * NE_ * 1024];   // [b*128+e][K(512)|V(512)]
__device__ float g_q [(size_t)BS_ * NAG * EMB];
__device__ float g_at[(size_t)BS_ * NAG * EMB];    // attention out (tf32-rounded)
__device__ float g_wr[3 * EMB * KDIM];             // W_in, tf32-rounded
__device__ float g_wor[EMB * EMB];                 // W_out, tf32-rounded

// ---------------- helpers ----------------------------------------------------
#define CP16(dst, src) \
    asm volatile("cp.async.cg.shared.global [%0], [%1], 16;" :: "r"(dst), "l"(src) : "memory")
#define CP_COMMIT()  asm volatile("cp.async.commit_group;" ::: "memory")
#define CP_WAIT(n)   asm volatile("cp.async.wait_group %0;" :: "n"(n) : "memory")

__device__ __forceinline__ uint32_t smem_u32(const void* p) {
    uint32_t a;
    asm("{ .reg .u64 t; cvta.to.shared.u64 t, %1; cvt.u32.u64 %0, t; }" : "=r"(a) : "l"(p));
    return a;
}
__device__ __forceinline__ float f2tf32f(float f) {
    uint32_t r;
    asm("cvt.rna.tf32.f32 %0, %1;" : "=r"(r) : "f"(f));
    return __uint_as_float(r);
}
__device__ __forceinline__ uint32_t cvt_tf32_u32(uint32_t raw) {
    uint32_t r;
    asm("cvt.rna.tf32.f32 %0, %1;" : "=r"(r) : "f"(__uint_as_float(raw)));
    return r;
}
__device__ __forceinline__ void mma_tf32(float* c, const uint32_t* a, const uint32_t* b) {
    asm volatile(
        "mma.sync.aligned.m16n8k8.row.col.f32.tf32.tf32.f32 "
        "{%0,%1,%2,%3}, {%4,%5,%6,%7}, {%8,%9}, {%0,%1,%2,%3};"
        : "+f"(c[0]), "+f"(c[1]), "+f"(c[2]), "+f"(c[3])
        : "r"(a[0]), "r"(a[1]), "r"(a[2]), "r"(a[3]), "r"(b[0]), "r"(b[1]));
}
__device__ __forceinline__ void mma_bf16(float* c, const uint32_t* a, const uint32_t* b) {
    asm volatile(
        "mma.sync.aligned.m16n8k16.row.col.f32.bf16.bf16.f32 "
        "{%0,%1,%2,%3}, {%4,%5,%6,%7}, {%8,%9}, {%0,%1,%2,%3};"
        : "+f"(c[0]), "+f"(c[1]), "+f"(c[2]), "+f"(c[3])
        : "r"(a[0]), "r"(a[1]), "r"(a[2]), "r"(a[3]), "r"(b[0]), "r"(b[1]));
}
// split two fp32 into packed bf16x2 hi and lo words (low half = first arg)
__device__ __forceinline__ void split2(float x, float y, uint32_t& hi, uint32_t& lo) {
    __nv_bfloat16 hx = __float2bfloat16(x), hy = __float2bfloat16(y);
    __nv_bfloat16 lx = __float2bfloat16(x - __bfloat162float(hx));
    __nv_bfloat16 ly = __float2bfloat16(y - __bfloat162float(hy));
    __nv_bfloat162 hp(hx, hy), lp(lx, ly);
    hi = *(uint32_t*)&hp; lo = *(uint32_t*)&lp;
}

// ---------------- tf32 rounding pre-pass (weights only) ---------------------
__global__ __launch_bounds__(256)
void round_tf32(const float* __restrict__ x, float* __restrict__ y, int n4)
{
    int i = blockIdx.x * 256 + threadIdx.x;
    if (i >= n4) return;
    float4 v = ((const float4*)x)[i];
    v.x = f2tf32f(v.x); v.y = f2tf32f(v.y);
    v.z = f2tf32f(v.z); v.w = f2tf32f(v.w);
    ((float4*)y)[i] = v;
}

// ---------------- TF32 GEMM body (warp 64x64, frag pipeline) ----------------
// C = A[*,512] * B[*,512]^T. B must be pre-rounded to tf32 patterns; A is
// cvt'd in-register iff CVT_A. CTA 128 thr (4 warps 2x2, each 64x64), BK=32,
// 3-stage cp.async ring, one barrier per chunk, 2-deep fragment pipeline.
#define FPITCH 36
#define ROWB   (FPITCH * 4)
#define MATB   (128 * ROWB)
#define STAGEB (2 * MATB)
#define NSTAGE 3

template<bool CVT_A>
__device__ __forceinline__ void gemm_body(
    const float* __restrict__ A, const float* __restrict__ B,
    float* __restrict__ C, int ldc, int tm, int tn, bool remap,
    bool final_, const float* __restrict__ bias, const int* __restrict__ rowmask,
    char* sm)
{
    const int tid  = threadIdx.x;
    const int wid  = tid >> 5, lane = tid & 31;
    const int wm   = wid >> 1, wn = wid & 1;
    const int lr4  = lane >> 2;
    const int lc   = lane & 3;

    const int rq = tid >> 2;
    const int qo = (tid & 3) << 2;

    const float* gA[4];
    const float* gB[4];
    #pragma unroll
    for (int k = 0; k < 4; k++) {
        int r = rq + 32 * k;
        int arow = tm * 128 + r;
        if (remap) arow = ((arow >> 5) << 7) | (arow & 31);
        gA[k] = A + (size_t)arow * KDIM + qo;
        gB[k] = B + (size_t)(tn * 128 + r) * KDIM + qo;
    }
    const uint32_t smb  = smem_u32(sm);
    const uint32_t dst0 = smb + rq * ROWB + qo * 4;

    float acc[4][8][4];
    #pragma unroll
    for (int i = 0; i < 4; i++)
        #pragma unroll
        for (int j = 0; j < 8; j++)
            #pragma unroll
            for (int k = 0; k < 4; k++) acc[i][j][k] = 0.f;

    auto issue = [&](int ch, int st) {
        const int koff = ch * 32;
        const uint32_t d = dst0 + st * STAGEB;
        #pragma unroll
        for (int k = 0; k < 4; k++) {
            const uint32_t dr = d + k * 32 * ROWB;
            CP16(dr,             gA[k] + koff);
            CP16(dr + 64,        gA[k] + koff + 16);
            CP16(dr + MATB,      gB[k] + koff);
            CP16(dr + MATB + 64, gB[k] + koff + 16);
        }
        CP_COMMIT();
    };

    issue(0, 0);
    issue(1, 1);

    const int warpRow = wm * 64;
    const int warpCol = wn * 64;

    uint32_t af[2][4][4], bf[2][8][2];

    #define LOAD_FRAGS(buf, ks, sA, sB) do {                                   \
        const int kb_ = (ks) * 32 + lc * 4;                                    \
        _Pragma("unroll")                                                      \
        for (int mt = 0; mt < 4; mt++) {                                       \
            int r_ = warpRow + mt * 16 + lr4;                                  \
            const char* p0_ = (sA) + r_ * ROWB + kb_;                          \
            const char* p1_ = (sA) + (r_ + 8) * ROWB + kb_;                    \
            uint32_t v0_ = *(const uint32_t*)p0_;                              \
            uint32_t v1_ = *(const uint32_t*)p1_;                              \
            uint32_t v2_ = *(const uint32_t*)(p0_ + 16);                       \
            uint32_t v3_ = *(const uint32_t*)(p1_ + 16);                       \
            if (CVT_A) {                                                       \
                v0_ = cvt_tf32_u32(v0_); v1_ = cvt_tf32_u32(v1_);              \
                v2_ = cvt_tf32_u32(v2_); v3_ = cvt_tf32_u32(v3_);              \
            }                                                                  \
            af[buf][mt][0] = v0_; af[buf][mt][1] = v1_;                        \
            af[buf][mt][2] = v2_; af[buf][mt][3] = v3_;                        \
        }                                                                      \
        _Pragma("unroll")                                                      \
        for (int nt = 0; nt < 8; nt++) {                                       \
            int c_ = warpCol + nt * 8 + lr4;                                   \
            const char* p_ = (sB) + c_ * ROWB + kb_;                           \
            bf[buf][nt][0] = *(const uint32_t*)p_;                             \
            bf[buf][nt][1] = *(const uint32_t*)(p_ + 16);                      \
        }                                                                      \
    } while (0)

    for (int ch = 0; ch < 16; ch++) {
        if (ch < 15) CP_WAIT(1); else CP_WAIT(0);
        __syncthreads();

        const int st = ch % NSTAGE;
        const char* sA = sm + st * STAGEB;
        const char* sB = sA + MATB;

        LOAD_FRAGS(0, 0, sA, sB);
        if (ch + 2 < 16) issue(ch + 2, (ch + 2) % 3);

        #pragma unroll
        for (int ks = 0; ks < 4; ks++) {
            const int cur = ks & 1;
            if (ks < 3) LOAD_FRAGS(cur ^ 1, ks + 1, sA, sB);
            #pragma unroll
            for (int mt = 0; mt < 4; mt++)
                #pragma unroll
                for (int nt = 0; nt < 8; nt++)
                    mma_tf32(acc[mt][nt], af[cur][mt], bf[cur][nt]);
        }
    }
    #undef LOAD_FRAGS

    #pragma unroll
    for (int mt = 0; mt < 4; mt++) {
        int r0 = tm * 128 + warpRow + mt * 16 + lr4;
        int r1 = r0 + 8;
        bool z0 = false, z1 = false;
        if (final_) { z0 = rowmask[r0] != 0; z1 = rowmask[r1] != 0; }
        #pragma unroll
        for (int nt = 0; nt < 8; nt++) {
            int c = tn * 128 + warpCol + nt * 8 + lc * 2;
            float2 v0 = make_float2(acc[mt][nt][0], acc[mt][nt][1]);
            float2 v1 = make_float2(acc[mt][nt][2], acc[mt][nt][3]);
            if (final_) {
                float2 bb = *(const float2*)(bias + c);
                if (z0) v0 = make_float2(0.f, 0.f);
                else    { v0.x += bb.x; v0.y += bb.y; }
                if (z1) v1 = make_float2(0.f, 0.f);
                else    { v1.x += bb.x; v1.y += bb.y; }
            }
            *(float2*)(C + (size_t)r0 * ldc + c) = v0;
            *(float2*)(C + (size_t)r1 * ldc + c) = v1;
        }
    }
}

__global__ __launch_bounds__(128, 2)
void gemm_kvq(const float* __restrict__ ent, const float* __restrict__ wr,
              float* __restrict__ kv, float* __restrict__ qo)
{
    extern __shared__ char sm[];
    const int bx = blockIdx.x, by = blockIdx.y;
    if (by < 1024) {
        gemm_body<true>(ent, wr + 512 * 512, kv, 1024, by, bx, false, false, nullptr, nullptr, sm);
    } else {
        int id = (by - 1024) * 8 + bx;
        gemm_body<true>(ent, wr, qo, 512, id >> 2, id & 3, true, false, nullptr, nullptr, sm);
    }
}

__global__ __launch_bounds__(128, 2)
void gemm_out(const float* __restrict__ A, const float* __restrict__ B,
              float* __restrict__ C,
              const float* __restrict__ bias, const int* __restrict__ rowmask)
{
    extern __shared__ char sm[];
    gemm_body<false>(A, B, C, 512, blockIdx.y, blockIdx.x, false, true, bias, rowmask, sm);
}

// ---------------- attention: bf16x3 tensor-core version ---------------------
// block = (b,h), 256 thr (8 warps). hi/lo bf16 smem tiles, 2 MMA phases.
#define OQH 0                    // qhi [32][36]
#define OQL 1152                 // qlo
#define OKH 2304                 // khi [128][36]
#define OKL 6912                 // klo
#define OVH 11520                // vt hi [64 d][68 e-pairs]
#define OVL 15872                // vt lo
#define OWH 20224                // w hi [32][68]
#define OWL 22400                // w lo
#define OU  24576                // union: v fp32 stage [128][21] / logits [32][132]
#define ATTN_WORDS 28800         // 115200 bytes

__global__ __launch_bounds__(256, 2)
void attn_kernel(const float* __restrict__ q, const float* __restrict__ kv,
                 const int* __restrict__ pre_mask, float* __restrict__ out)
{
    extern __shared__ uint32_t smw[];
    float* smf = (float*)smw;
    const int tid = threadIdx.x;
    const int wid = tid >> 5, lane = tid & 31;
    const int lr4 = lane >> 2, lc = lane & 3;
    const int wm  = wid >> 2, wn = wid & 3;          // warp grid 2x4
    const int b = blockIdx.x >> 3;
    const int h = blockIdx.x & 7;

    const float* qbase = q  + (size_t)b * (NAG * EMB) + h * HDD;
    const float* kbase = kv + (size_t)b * (NE_ * 1024) + h * HDD;
    const float* vbase = kbase + EMB;

    // P1: q -> qhi/qlo bf16 pairs
    #pragma unroll
    for (int it = 0; it < 4; it++) {
        int i = tid + it * 256;
        int a = i >> 5, wd = i & 31;
        float2 x = *(const float2*)(qbase + (size_t)a * EMB + wd * 2);
        uint32_t hi, lo; split2(x.x, x.y, hi, lo);
        smw[OQH + a * 36 + wd] = hi;
        smw[OQL + a * 36 + wd] = lo;
    }
    // P2: k -> khi/klo
    #pragma unroll
    for (int it = 0; it < 16; it++) {
        int i = tid + it * 256;
        int e = i >> 5, wd = i & 31;
        float2 x = *(const float2*)(kbase + (size_t)e * 1024 + wd * 2);
        uint32_t hi, lo; split2(x.x, x.y, hi, lo);
        smw[OKH + e * 36 + wd] = hi;
        smw[OKL + e * 36 + wd] = lo;
    }
    // P3: v -> transposed vt hi/lo, via fp32 staging in 4 d-quarters
    for (int dq = 0; dq < 4; dq++) {
        const int d0 = dq * 16;
        #pragma unroll
        for (int it = 0; it < 2; it++) {
            int i = tid + it * 256;
            int e = i >> 2, f = (i & 3) * 4;
            float4 x = *(const float4*)(vbase + (size_t)e * 1024 + d0 + f);
            float* s = smf + OU + e * 21 + f;
            s[0] = x.x; s[1] = x.y; s[2] = x.z; s[3] = x.w;
        }
        __syncthreads();
        #pragma unroll
        for (int it = 0; it < 4; it++) {
            int i = tid + it * 256;
            int dl = i >> 6, ep = i & 63;
            float a0 = smf[OU + (2 * ep)     * 21 + dl];
            float a1 = smf[OU + (2 * ep + 1) * 21 + dl];
            uint32_t hi, lo; split2(a0, a1, hi, lo);
            smw[OVH + (d0 + dl) * 68 + ep] = hi;
            smw[OVL + (d0 + dl) * 68 + ep] = lo;
        }
        __syncthreads();
    }

    // P4: logits = q @ k^T (bf16x3), warp tile 16a x 32e, K=64
    float lg[4][4];
    #pragma unroll
    for (int i = 0; i < 4; i++)
        #pragma unroll
        for (int j = 0; j < 4; j++) lg[i][j] = 0.f;

    const int rowA = wm * 16 + lr4;
    #pragma unroll
    for (int ks = 0; ks < 4; ks++) {
        const int kw = lc + ks * 8;
        uint32_t ah[4], al[4];
        ah[0] = smw[OQH + rowA * 36 + kw];       al[0] = smw[OQL + rowA * 36 + kw];
        ah[1] = smw[OQH + (rowA + 8) * 36 + kw]; al[1] = smw[OQL + (rowA + 8) * 36 + kw];
        ah[2] = smw[OQH + rowA * 36 + kw + 4];   al[2] = smw[OQL + rowA * 36 + kw + 4];
        ah[3] = smw[OQH + (rowA + 8) * 36 + kw + 4]; al[3] = smw[OQL + (rowA + 8) * 36 + kw + 4];
        #pragma unroll
        for (int nt = 0; nt < 4; nt++) {
            int col = wn * 32 + nt * 8 + lr4;
            uint32_t bh[2], bl[2];
            bh[0] = smw[OKH + col * 36 + kw];     bh[1] = smw[OKH + col * 36 + kw + 4];
            bl[0] = smw[OKL + col * 36 + kw];     bl[1] = smw[OKL + col * 36 + kw + 4];
            mma_bf16(lg[nt], ah, bh);
            mma_bf16(lg[nt], ah, bl);
            mma_bf16(lg[nt], al, bh);
        }
    }

    // P5: masked, scaled logits -> fp32 smem (pitch 132)
    {
        const int* mb = pre_mask + (size_t)b * (NAG * NE_);
        int r0 = wm * 16 + lr4, r1 = r0 + 8;
        #pragma unroll
        for (int nt = 0; nt < 4; nt++) {
            int c = wn * 32 + nt * 8 + lc * 2;
            int2 m0 = *(const int2*)(mb + r0 * NE_ + c);
            int2 m1 = *(const int2*)(mb + r1 * NE_ + c);
            smf[OU + r0 * 132 + c]     = m0.x ? -1e30f : lg[nt][0] * 0.125f;
            smf[OU + r0 * 132 + c + 1] = m0.y ? -1e30f : lg[nt][1] * 0.125f;
            smf[OU + r1 * 132 + c]     = m1.x ? -1e30f : lg[nt][2] * 0.125f;
            smf[OU + r1 * 132 + c + 1] = m1.y ? -1e30f : lg[nt][3] * 0.125f;
        }
    }
    __syncthreads();

    // P6: softmax over e (8 threads per agent row)
    {
        int a = tid >> 3, l = tid & 7;
        float* row = smf + OU + a * 132;
        float mx = -1e30f;
        #pragma unroll
        for (int j = 0; j < 16; j++) mx = fmaxf(mx, row[l + 8 * j]);
        mx = fmaxf(mx, __shfl_xor_sync(0xffffffffu, mx, 1));
        mx = fmaxf(mx, __shfl_xor_sync(0xffffffffu, mx, 2));
        mx = fmaxf(mx, __shfl_xor_sync(0xffffffffu, mx, 4));
        float ex[16], sum = 0.f;
        #pragma unroll
        for (int j = 0; j < 16; j++) { float t = __expf(row[l + 8 * j] - mx); ex[j] = t; sum += t; }
        sum += __shfl_xor_sync(0xffffffffu, sum, 1);
        sum += __shfl_xor_sync(0xffffffffu, sum, 2);
        sum += __shfl_xor_sync(0xffffffffu, sum, 4);
        float inv = (mx <= -1e29f) ? 0.f : (1.0f / sum);
        #pragma unroll
        for (int j = 0; j < 16; j++) row[l + 8 * j] = ex[j] * inv;
    }
    __syncthreads();

    // P7: w -> whi/wlo bf16 pairs
    #pragma unroll
    for (int it = 0; it < 8; it++) {
        int i = tid + it * 256;
        int a = i >> 6, ep = i & 63;
        float2 x = *(const float2*)(smf + OU + a * 132 + 2 * ep);
        uint32_t hi, lo; split2(x.x, x.y, hi, lo);
        smw[OWH + a * 68 + ep] = hi;
        smw[OWL + a * 68 + ep] = lo;
    }
    __syncthreads();

    // P8: attn = w @ v (bf16x3), warp tile 16a x 16d, K=128
    float oa[2][4];
    #pragma unroll
    for (int i = 0; i < 2; i++)
        #pragma unroll
        for (int j = 0; j < 4; j++) oa[i][j] = 0.f;

    #pragma unroll
    for (int ks = 0; ks < 8; ks++) {
        const int kw = lc + ks * 8;
        uint32_t ah[4], al[4];
        ah[0] = smw[OWH + rowA * 68 + kw];           al[0] = smw[OWL + rowA * 68 + kw];
        ah[1] = smw[OWH + (rowA + 8) * 68 + kw];     al[1] = smw[OWL + (rowA + 8) * 68 + kw];
        ah[2] = smw[OWH + rowA * 68 + kw + 4];       al[2] = smw[OWL + rowA * 68 + kw + 4];
        ah[3] = smw[OWH + (rowA + 8) * 68 + kw + 4]; al[3] = smw[OWL + (rowA + 8) * 68 + kw + 4];
        #pragma unroll
        for (int nt = 0; nt < 2; nt++) {
            int col = wn * 16 + nt * 8 + lr4;
            uint32_t bh[2], bl[2];
            bh[0] = smw[OVH + col * 68 + kw];  bh[1] = smw[OVH + col * 68 + kw + 4];
            bl[0] = smw[OVL + col * 68 + kw];  bl[1] = smw[OVL + col * 68 + kw + 4];
            mma_bf16(oa[nt], ah, bh);
            mma_bf16(oa[nt], ah, bl);
            mma_bf16(oa[nt], al, bh);
        }
    }

    // P9: write attn out, tf32-rounded (out-GEMM A operand loads raw)
    float* ob = out + (size_t)b * (NAG * EMB) + h * HDD;
    #pragma unroll
    for (int nt = 0; nt < 2; nt++) {
        int d0 = wn * 16 + nt * 8 + lc * 2;
        *(float2*)(ob + (size_t)rowA * EMB + d0) =
            make_float2(f2tf32f(oa[nt][0]), f2tf32f(oa[nt][1]));
        *(float2*)(ob + (size_t)(rowA + 8) * EMB + d0) =
            make_float2(f2tf32f(oa[nt][2]), f2tf32f(oa[nt][3]));
    }
}

// ---------------- launch ---------------------------------------------------
extern "C" void kernel_launch(void* const* d_in, const int* in_sizes, int n_in,
                              void* d_out, int out_size)
{
    const float* entities  = (const float*)d_in[0];
    const int*   pre_mask  = (const int*)d_in[1];
    const int*   post_mask = (const int*)d_in[2];
    const float* W_in      = (const float*)d_in[3];
    const float* W_out     = (const float*)d_in[4];
    const float* b_out     = (const float*)d_in[5];
    float*       out       = (float*)d_out;

    float *kv_p, *q_p, *at_p, *wr_p, *wor_p;
    cudaGetSymbolAddress((void**)&kv_p,  g_kv);
    cudaGetSymbolAddress((void**)&q_p,   g_q);
    cudaGetSymbolAddress((void**)&at_p,  g_at);
    cudaGetSymbolAddress((void**)&wr_p,  g_wr);
    cudaGetSymbolAddress((void**)&wor_p, g_wor);

    const int SMEM_BYTES = NSTAGE * STAGEB;       // 110592
    const int ATTN_BYTES = ATTN_WORDS * 4;        // 115200
    cudaFuncSetAttribute(gemm_kvq,    cudaFuncAttributeMaxDynamicSharedMemorySize, SMEM_BYTES);
    cudaFuncSetAttribute(gemm_out,    cudaFuncAttributeMaxDynamicSharedMemorySize, SMEM_BYTES);
    cudaFuncSetAttribute(attn_kernel, cudaFuncAttributeMaxDynamicSharedMemorySize, ATTN_BYTES);

    // tf32 rounding pre-pass (weights only; tiny)
    round_tf32<<<(3*EMB*KDIM/4 + 255)/256, 256>>>(W_in,  wr_p,  3*EMB*KDIM/4);
    round_tf32<<<(EMB*EMB/4    + 255)/256, 256>>>(W_out, wor_p, EMB*EMB/4);

    // merged K|V projection (y<1024) + Q projection (y>=1024)
    gemm_kvq<<<dim3(8, 1152), 128, SMEM_BYTES>>>(entities, wr_p, kv_p, q_p);

    // tensor-core attention (bf16x3; writes tf32-rounded output)
    attn_kernel<<<BS_ * NHD, 256, ATTN_BYTES>>>(q_p, kv_p, pre_mask, at_p);

    // out GEMM + bias + post-mask (no A cvt needed)
    gemm_out<<<dim3(4, 256), 128, SMEM_BYTES>>>(at_p, wor_p, out, b_out, post_mask);
}

// round 12
// speedup vs baseline: 2.8273x; 1.0411x over previous
#include <cuda_runtime.h>
#include <cuda_bf16.h>
#include <cstdint>

#define BS_   1024
#define NE_   128
#define EMB   512
#define NAG   32
#define NHD   8
#define HDD   64
#define KDIM  512

// ---------------- scratch (device globals; allocation-guard safe) ----------
__device__ float g_kv[(size_t)BS_ * NE_ * 1024];   // [b*128+e][K(512)|V(512)]
__device__ float g_q [(size_t)BS_ * NAG * EMB];
__device__ float g_at[(size_t)BS_ * NAG * EMB];    // attention out (tf32-rounded)
__device__ float g_wr[3 * EMB * KDIM];             // W_in, tf32-rounded
__device__ float g_wor[EMB * EMB];                 // W_out, tf32-rounded

// ---------------- helpers ----------------------------------------------------
#define CP16(dst, src) \
    asm volatile("cp.async.cg.shared.global [%0], [%1], 16;" :: "r"(dst), "l"(src) : "memory")
#define CP_COMMIT()  asm volatile("cp.async.commit_group;" ::: "memory")
#define CP_WAIT(n)   asm volatile("cp.async.wait_group %0;" :: "n"(n) : "memory")

__device__ __forceinline__ uint32_t smem_u32(const void* p) {
    uint32_t a;
    asm("{ .reg .u64 t; cvta.to.shared.u64 t, %1; cvt.u32.u64 %0, t; }" : "=r"(a) : "l"(p));
    return a;
}
__device__ __forceinline__ float f2tf32f(float f) {
    uint32_t r;
    asm("cvt.rna.tf32.f32 %0, %1;" : "=r"(r) : "f"(f));
    return __uint_as_float(r);
}
__device__ __forceinline__ uint32_t cvt_tf32_u32(uint32_t raw) {
    uint32_t r;
    asm("cvt.rna.tf32.f32 %0, %1;" : "=r"(r) : "f"(__uint_as_float(raw)));
    return r;
}
__device__ __forceinline__ void mma_tf32(float* c, const uint32_t* a, const uint32_t* b) {
    asm volatile(
        "mma.sync.aligned.m16n8k8.row.col.f32.tf32.tf32.f32 "
        "{%0,%1,%2,%3}, {%4,%5,%6,%7}, {%8,%9}, {%0,%1,%2,%3};"
        : "+f"(c[0]), "+f"(c[1]), "+f"(c[2]), "+f"(c[3])
        : "r"(a[0]), "r"(a[1]), "r"(a[2]), "r"(a[3]), "r"(b[0]), "r"(b[1]));
}
__device__ __forceinline__ void mma_bf16(float* c, const uint32_t* a, const uint32_t* b) {
    asm volatile(
        "mma.sync.aligned.m16n8k16.row.col.f32.bf16.bf16.f32 "
        "{%0,%1,%2,%3}, {%4,%5,%6,%7}, {%8,%9}, {%0,%1,%2,%3};"
        : "+f"(c[0]), "+f"(c[1]), "+f"(c[2]), "+f"(c[3])
        : "r"(a[0]), "r"(a[1]), "r"(a[2]), "r"(a[3]), "r"(b[0]), "r"(b[1]));
}
// split two fp32 into packed bf16x2 hi and lo words (low half = first arg)
__device__ __forceinline__ void split2(float x, float y, uint32_t& hi, uint32_t& lo) {
    asm("cvt.rn.bf16x2.f32 %0, %1, %2;" : "=r"(hi) : "f"(y), "f"(x));
    float hx = __uint_as_float(hi << 16);
    float hy = __uint_as_float(hi & 0xffff0000u);
    asm("cvt.rn.bf16x2.f32 %0, %1, %2;" : "=r"(lo) : "f"(y - hy), "f"(x - hx));
}

// ---------------- tf32 rounding pre-pass (weights only) ---------------------
__global__ __launch_bounds__(256)
void round_tf32(const float* __restrict__ x, float* __restrict__ y, int n4)
{
    int i = blockIdx.x * 256 + threadIdx.x;
    if (i >= n4) return;
    float4 v = ((const float4*)x)[i];
    v.x = f2tf32f(v.x); v.y = f2tf32f(v.y);
    v.z = f2tf32f(v.z); v.w = f2tf32f(v.w);
    ((float4*)y)[i] = v;
}

// ---------------- TF32 GEMM body (warp 64x64, frag pipeline) ----------------
// C = A[*,512] * B[*,512]^T. B must be pre-rounded to tf32 patterns; A is
// cvt'd in-register iff CVT_A. CTA 128 thr (4 warps 2x2, each 64x64), BK=32,
// 3-stage cp.async ring, one barrier per chunk, 2-deep fragment pipeline.
#define FPITCH 36
#define ROWB   (FPITCH * 4)
#define MATB   (128 * ROWB)
#define STAGEB (2 * MATB)
#define NSTAGE 3

template<bool CVT_A>
__device__ __forceinline__ void gemm_body(
    const float* __restrict__ A, const float* __restrict__ B,
    float* __restrict__ C, int ldc, int tm, int tn, bool remap,
    bool final_, const float* __restrict__ bias, const int* __restrict__ rowmask,
    char* sm)
{
    const int tid  = threadIdx.x;
    const int wid  = tid >> 5, lane = tid & 31;
    const int wm   = wid >> 1, wn = wid & 1;
    const int lr4  = lane >> 2;
    const int lc   = lane & 3;

    const int rq = tid >> 2;
    const int qo = (tid & 3) << 2;

    const float* gA[4];
    const float* gB[4];
    #pragma unroll
    for (int k = 0; k < 4; k++) {
        int r = rq + 32 * k;
        int arow = tm * 128 + r;
        if (remap) arow = ((arow >> 5) << 7) | (arow & 31);
        gA[k] = A + (size_t)arow * KDIM + qo;
        gB[k] = B + (size_t)(tn * 128 + r) * KDIM + qo;
    }
    const uint32_t smb  = smem_u32(sm);
    const uint32_t dst0 = smb + rq * ROWB + qo * 4;

    float acc[4][8][4];
    #pragma unroll
    for (int i = 0; i < 4; i++)
        #pragma unroll
        for (int j = 0; j < 8; j++)
            #pragma unroll
            for (int k = 0; k < 4; k++) acc[i][j][k] = 0.f;

    auto issue = [&](int ch, int st) {
        const int koff = ch * 32;
        const uint32_t d = dst0 + st * STAGEB;
        #pragma unroll
        for (int k = 0; k < 4; k++) {
            const uint32_t dr = d + k * 32 * ROWB;
            CP16(dr,             gA[k] + koff);
            CP16(dr + 64,        gA[k] + koff + 16);
            CP16(dr + MATB,      gB[k] + koff);
            CP16(dr + MATB + 64, gB[k] + koff + 16);
        }
        CP_COMMIT();
    };

    issue(0, 0);
    issue(1, 1);

    const int warpRow = wm * 64;
    const int warpCol = wn * 64;

    uint32_t af[2][4][4], bf[2][8][2];

    #define LOAD_FRAGS(buf, ks, sA, sB) do {                                   \
        const int kb_ = (ks) * 32 + lc * 4;                                    \
        _Pragma("unroll")                                                      \
        for (int mt = 0; mt < 4; mt++) {                                       \
            int r_ = warpRow + mt * 16 + lr4;                                  \
            const char* p0_ = (sA) + r_ * ROWB + kb_;                          \
            const char* p1_ = (sA) + (r_ + 8) * ROWB + kb_;                    \
            uint32_t v0_ = *(const uint32_t*)p0_;                              \
            uint32_t v1_ = *(const uint32_t*)p1_;                              \
            uint32_t v2_ = *(const uint32_t*)(p0_ + 16);                       \
            uint32_t v3_ = *(const uint32_t*)(p1_ + 16);                       \
            if (CVT_A) {                                                       \
                v0_ = cvt_tf32_u32(v0_); v1_ = cvt_tf32_u32(v1_);              \
                v2_ = cvt_tf32_u32(v2_); v3_ = cvt_tf32_u32(v3_);              \
            }                                                                  \
            af[buf][mt][0] = v0_; af[buf][mt][1] = v1_;                        \
            af[buf][mt][2] = v2_; af[buf][mt][3] = v3_;                        \
        }                                                                      \
        _Pragma("unroll")                                                      \
        for (int nt = 0; nt < 8; nt++) {                                       \
            int c_ = warpCol + nt * 8 + lr4;                                   \
            const char* p_ = (sB) + c_ * ROWB + kb_;                           \
            bf[buf][nt][0] = *(const uint32_t*)p_;                             \
            bf[buf][nt][1] = *(const uint32_t*)(p_ + 16);                      \
        }                                                                      \
    } while (0)

    for (int ch = 0; ch < 16; ch++) {
        if (ch < 15) CP_WAIT(1); else CP_WAIT(0);
        __syncthreads();

        const int st = ch % NSTAGE;
        const char* sA = sm + st * STAGEB;
        const char* sB = sA + MATB;

        LOAD_FRAGS(0, 0, sA, sB);
        if (ch + 2 < 16) issue(ch + 2, (ch + 2) % 3);

        #pragma unroll
        for (int ks = 0; ks < 4; ks++) {
            const int cur = ks & 1;
            if (ks < 3) LOAD_FRAGS(cur ^ 1, ks + 1, sA, sB);
            #pragma unroll
            for (int mt = 0; mt < 4; mt++)
                #pragma unroll
                for (int nt = 0; nt < 8; nt++)
                    mma_tf32(acc[mt][nt], af[cur][mt], bf[cur][nt]);
        }
    }
    #undef LOAD_FRAGS

    #pragma unroll
    for (int mt = 0; mt < 4; mt++) {
        int r0 = tm * 128 + warpRow + mt * 16 + lr4;
        int r1 = r0 + 8;
        bool z0 = false, z1 = false;
        if (final_) { z0 = rowmask[r0] != 0; z1 = rowmask[r1] != 0; }
        #pragma unroll
        for (int nt = 0; nt < 8; nt++) {
            int c = tn * 128 + warpCol + nt * 8 + lc * 2;
            float2 v0 = make_float2(acc[mt][nt][0], acc[mt][nt][1]);
            float2 v1 = make_float2(acc[mt][nt][2], acc[mt][nt][3]);
            if (final_) {
                float2 bb = *(const float2*)(bias + c);
                if (z0) v0 = make_float2(0.f, 0.f);
                else    { v0.x += bb.x; v0.y += bb.y; }
                if (z1) v1 = make_float2(0.f, 0.f);
                else    { v1.x += bb.x; v1.y += bb.y; }
            }
            *(float2*)(C + (size_t)r0 * ldc + c) = v0;
            *(float2*)(C + (size_t)r1 * ldc + c) = v1;
        }
    }
}

__global__ __launch_bounds__(128, 2)
void gemm_kvq(const float* __restrict__ ent, const float* __restrict__ wr,
              float* __restrict__ kv, float* __restrict__ qo)
{
    extern __shared__ char sm[];
    const int bx = blockIdx.x, by = blockIdx.y;
    if (by < 1024) {
        gemm_body<true>(ent, wr + 512 * 512, kv, 1024, by, bx, false, false, nullptr, nullptr, sm);
    } else {
        int id = (by - 1024) * 8 + bx;
        gemm_body<true>(ent, wr, qo, 512, id >> 2, id & 3, true, false, nullptr, nullptr, sm);
    }
}

__global__ __launch_bounds__(128, 2)
void gemm_out(const float* __restrict__ A, const float* __restrict__ B,
              float* __restrict__ C,
              const float* __restrict__ bias, const int* __restrict__ rowmask)
{
    extern __shared__ char sm[];
    gemm_body<false>(A, B, C, 512, blockIdx.y, blockIdx.x, false, true, bias, rowmask, sm);
}

// ---------------- attention: bf16x3 tensor-core, overlaid smem --------------
// block = (b,h), 256 thr (8 warps, grid 2x4). 5 barriers total.
// Region A (q/k, dead after logits MMA) is overlaid by logits + w.
#define OQH 0                    // qhi [32][36]
#define OQL 1152                 // qlo
#define OKH 2304                 // khi [128][36]
#define OKL 6912                 // klo          -> 11520
#define OVH 11520                // vt hi [64 d][68 e-pairs]
#define OVL 15872                // vt lo        -> 20224
#define OU  0                    // overlay: logits [32][132] = 4224
#define OWH 4224                 // overlay: w hi [32][68]
#define OWL 6400                 // overlay: w lo -> 8576 (< 11520, fits)
#define ATTN_WORDS 20224         // 80896 bytes

__global__ __launch_bounds__(256, 2)
void attn_kernel(const float* __restrict__ q, const float* __restrict__ kv,
                 const int* __restrict__ pre_mask, float* __restrict__ out)
{
    extern __shared__ uint32_t smw[];
    float* smf = (float*)smw;
    const int tid = threadIdx.x;
    const int wid = tid >> 5, lane = tid & 31;
    const int lr4 = lane >> 2, lc = lane & 3;
    const int wm  = wid >> 2, wn = wid & 3;          // warp grid 2x4
    const int b = blockIdx.x >> 3;
    const int h = blockIdx.x & 7;

    const float* qbase = q  + (size_t)b * (NAG * EMB) + h * HDD;
    const float* kbase = kv + (size_t)b * (NE_ * 1024) + h * HDD;
    const float* vbase = kbase + EMB;
    const int rowA = wm * 16 + lr4;

    // P0: prefetch pre-mask into registers (hides L2/DRAM latency behind converts)
    const int* mb = pre_mask + (size_t)b * (NAG * NE_);
    int2 pm0[4], pm1[4];
    #pragma unroll
    for (int nt = 0; nt < 4; nt++) {
        int c = wn * 32 + nt * 8 + lc * 2;
        pm0[nt] = *(const int2*)(mb + rowA * NE_ + c);
        pm1[nt] = *(const int2*)(mb + (rowA + 8) * NE_ + c);
    }

    // P1: q -> qhi/qlo bf16 pairs
    #pragma unroll
    for (int it = 0; it < 4; it++) {
        int i = tid + it * 256;
        int a = i >> 5, wd = i & 31;
        float2 x = *(const float2*)(qbase + (size_t)a * EMB + wd * 2);
        uint32_t hi, lo; split2(x.x, x.y, hi, lo);
        smw[OQH + a * 36 + wd] = hi;
        smw[OQL + a * 36 + wd] = lo;
    }
    // P2: k -> khi/klo
    #pragma unroll
    for (int it = 0; it < 16; it++) {
        int i = tid + it * 256;
        int e = i >> 5, wd = i & 31;
        float2 x = *(const float2*)(kbase + (size_t)e * 1024 + wd * 2);
        uint32_t hi, lo; split2(x.x, x.y, hi, lo);
        smw[OKH + e * 36 + wd] = hi;
        smw[OKL + e * 36 + wd] = lo;
    }
    // P3: v -> transposed vt hi/lo via paired-lane shuffle (no staging)
    // lane 2j loads row E, lane 2j+1 loads row E+1, 128B coalesced per row.
    #pragma unroll
    for (int it = 0; it < 16; it++) {
        int slot  = wid + it * 8;          // 0..127
        int epair = slot & 63;
        int fh    = slot >> 6;             // 0 or 1
        int f2    = fh * 16 + (lane >> 1); // 0..31 (float2 index along d)
        int e     = 2 * epair + (lane & 1);
        float2 x  = *(const float2*)(vbase + (size_t)e * 1024 + 2 * f2);
        float2 y;
        y.x = __shfl_xor_sync(0xffffffffu, x.x, 1);
        y.y = __shfl_xor_sync(0xffffffffu, x.y, 1);
        uint32_t hi, lo;
        int d;
        if (lane & 1) { split2(y.y, x.y, hi, lo); d = 2 * f2 + 1; }
        else          { split2(x.x, y.x, hi, lo); d = 2 * f2; }
        smw[OVH + d * 68 + epair] = hi;
        smw[OVL + d * 68 + epair] = lo;
    }
    __syncthreads();

    // P4: logits = q @ k^T (bf16x3), warp tile 16a x 32e, K=64
    float lg[4][4];
    #pragma unroll
    for (int i = 0; i < 4; i++)
        #pragma unroll
        for (int j = 0; j < 4; j++) lg[i][j] = 0.f;

    #pragma unroll
    for (int ks = 0; ks < 4; ks++) {
        const int kw = lc + ks * 8;
        uint32_t ah[4], al[4];
        ah[0] = smw[OQH + rowA * 36 + kw];       al[0] = smw[OQL + rowA * 36 + kw];
        ah[1] = smw[OQH + (rowA + 8) * 36 + kw]; al[1] = smw[OQL + (rowA + 8) * 36 + kw];
        ah[2] = smw[OQH + rowA * 36 + kw + 4];   al[2] = smw[OQL + rowA * 36 + kw + 4];
        ah[3] = smw[OQH + (rowA + 8) * 36 + kw + 4]; al[3] = smw[OQL + (rowA + 8) * 36 + kw + 4];
        #pragma unroll
        for (int nt = 0; nt < 4; nt++) {
            int col = wn * 32 + nt * 8 + lr4;
            uint32_t bh[2], bl[2];
            bh[0] = smw[OKH + col * 36 + kw];     bh[1] = smw[OKH + col * 36 + kw + 4];
            bl[0] = smw[OKL + col * 36 + kw];     bl[1] = smw[OKL + col * 36 + kw + 4];
            mma_bf16(lg[nt], ah, bh);
            mma_bf16(lg[nt], ah, bl);
            mma_bf16(lg[nt], al, bh);
        }
    }
    __syncthreads();   // q/k reads complete before overlay writes below

    // P5: masked, scaled logits -> overlay smem (pitch 132), masks from regs
    {
        int r0 = rowA, r1 = rowA + 8;
        #pragma unroll
        for (int nt = 0; nt < 4; nt++) {
            int c = wn * 32 + nt * 8 + lc * 2;
            smf[OU + r0 * 132 + c]     = pm0[nt].x ? -1e30f : lg[nt][0] * 0.125f;
            smf[OU + r0 * 132 + c + 1] = pm0[nt].y ? -1e30f : lg[nt][1] * 0.125f;
            smf[OU + r1 * 132 + c]     = pm1[nt].x ? -1e30f : lg[nt][2] * 0.125f;
            smf[OU + r1 * 132 + c + 1] = pm1[nt].y ? -1e30f : lg[nt][3] * 0.125f;
        }
    }
    __syncthreads();

    // P6: softmax over e (8 threads per agent row)
    {
        int a = tid >> 3, l = tid & 7;
        float* row = smf + OU + a * 132;
        float mx = -1e30f;
        #pragma unroll
        for (int j = 0; j < 16; j++) mx = fmaxf(mx, row[l + 8 * j]);
        mx = fmaxf(mx, __shfl_xor_sync(0xffffffffu, mx, 1));
        mx = fmaxf(mx, __shfl_xor_sync(0xffffffffu, mx, 2));
        mx = fmaxf(mx, __shfl_xor_sync(0xffffffffu, mx, 4));
        float ex[16], sum = 0.f;
        #pragma unroll
        for (int j = 0; j < 16; j++) { float t = __expf(row[l + 8 * j] - mx); ex[j] = t; sum += t; }
        sum += __shfl_xor_sync(0xffffffffu, sum, 1);
        sum += __shfl_xor_sync(0xffffffffu, sum, 2);
        sum += __shfl_xor_sync(0xffffffffu, sum, 4);
        float inv = (mx <= -1e29f) ? 0.f : (1.0f / sum);
        #pragma unroll
        for (int j = 0; j < 16; j++) row[l + 8 * j] = ex[j] * inv;
    }
    __syncthreads();

    // P7: w -> whi/wlo bf16 pairs (overlay region)
    #pragma unroll
    for (int it = 0; it < 8; it++) {
        int i = tid + it * 256;
        int a = i >> 6, ep = i & 63;
        float2 x = *(const float2*)(smf + OU + a * 132 + 2 * ep);
        uint32_t hi, lo; split2(x.x, x.y, hi, lo);
        smw[OWH + a * 68 + ep] = hi;
        smw[OWL + a * 68 + ep] = lo;
    }
    __syncthreads();

    // P8: attn = w @ v (bf16x3), warp tile 16a x 16d, K=128
    float oa[2][4];
    #pragma unroll
    for (int i = 0; i < 2; i++)
        #pragma unroll
        for (int j = 0; j < 4; j++) oa[i][j] = 0.f;

    #pragma unroll
    for (int ks = 0; ks < 8; ks++) {
        const int kw = lc + ks * 8;
        uint32_t ah[4], al[4];
        ah[0] = smw[OWH + rowA * 68 + kw];           al[0] = smw[OWL + rowA * 68 + kw];
        ah[1] = smw[OWH + (rowA + 8) * 68 + kw];     al[1] = smw[OWL + (rowA + 8) * 68 + kw];
        ah[2] = smw[OWH + rowA * 68 + kw + 4];       al[2] = smw[OWL + rowA * 68 + kw + 4];
        ah[3] = smw[OWH + (rowA + 8) * 68 + kw + 4]; al[3] = smw[OWL + (rowA + 8) * 68 + kw + 4];
        #pragma unroll
        for (int nt = 0; nt < 2; nt++) {
            int col = wn * 16 + nt * 8 + lr4;
            uint32_t bh[2], bl[2];
            bh[0] = smw[OVH + col * 68 + kw];  bh[1] = smw[OVH + col * 68 + kw + 4];
            bl[0] = smw[OVL + col * 68 + kw];  bl[1] = smw[OVL + col * 68 + kw + 4];
            mma_bf16(oa[nt], ah, bh);
            mma_bf16(oa[nt], ah, bl);
            mma_bf16(oa[nt], al, bh);
        }
    }

    // P9: write attn out, tf32-rounded (out-GEMM A operand loads raw)
    float* ob = out + (size_t)b * (NAG * EMB) + h * HDD;
    #pragma unroll
    for (int nt = 0; nt < 2; nt++) {
        int d0 = wn * 16 + nt * 8 + lc * 2;
        *(float2*)(ob + (size_t)rowA * EMB + d0) =
            make_float2(f2tf32f(oa[nt][0]), f2tf32f(oa[nt][1]));
        *(float2*)(ob + (size_t)(rowA + 8) * EMB + d0) =
            make_float2(f2tf32f(oa[nt][2]), f2tf32f(oa[nt][3]));
    }
}

// ---------------- launch ---------------------------------------------------
extern "C" void kernel_launch(void* const* d_in, const int* in_sizes, int n_in,
                              void* d_out, int out_size)
{
    const float* entities  = (const float*)d_in[0];
    const int*   pre_mask  = (const int*)d_in[1];
    const int*   post_mask = (const int*)d_in[2];
    const float* W_in      = (const float*)d_in[3];
    const float* W_out     = (const float*)d_in[4];
    const float* b_out     = (const float*)d_in[5];
    float*       out       = (float*)d_out;

    float *kv_p, *q_p, *at_p, *wr_p, *wor_p;
    cudaGetSymbolAddress((void**)&kv_p,  g_kv);
    cudaGetSymbolAddress((void**)&q_p,   g_q);
    cudaGetSymbolAddress((void**)&at_p,  g_at);
    cudaGetSymbolAddress((void**)&wr_p,  g_wr);
    cudaGetSymbolAddress((void**)&wor_p, g_wor);

    const int SMEM_BYTES = NSTAGE * STAGEB;       // 110592
    const int ATTN_BYTES = ATTN_WORDS * 4;        // 80896
    cudaFuncSetAttribute(gemm_kvq,    cudaFuncAttributeMaxDynamicSharedMemorySize, SMEM_BYTES);
    cudaFuncSetAttribute(gemm_out,    cudaFuncAttributeMaxDynamicSharedMemorySize, SMEM_BYTES);
    cudaFuncSetAttribute(attn_kernel, cudaFuncAttributeMaxDynamicSharedMemorySize, ATTN_BYTES);

    // tf32 rounding pre-pass (weights only; tiny)
    round_tf32<<<(3*EMB*KDIM/4 + 255)/256, 256>>>(W_in,  wr_p,  3*EMB*KDIM/4);
    round_tf32<<<(EMB*EMB/4    + 255)/256, 256>>>(W_out, wor_p, EMB*EMB/4);

    // merged K|V projection (y<1024) + Q projection (y>=1024)
    gemm_kvq<<<dim3(8, 1152), 128, SMEM_BYTES>>>(entities, wr_p, kv_p, q_p);

    // tensor-core attention (bf16x3; writes tf32-rounded output)
    attn_kernel<<<BS_ * NHD, 256, ATTN_BYTES>>>(q_p, kv_p, pre_mask, at_p);

    // out GEMM + bias + post-mask (no A cvt needed)
    gemm_out<<<dim3(4, 256), 128, SMEM_BYTES>>>(at_p, wor_p, out, b_out, post_mask);
}